// round 7
// baseline (speedup 1.0000x reference)
#include <cuda_runtime.h>
#include <cuda_bf16.h>
#include <cstdint>

// Problem constants
#define BB 4
#define LL 64
#define SS 64
#define NN 768
#define DD 64
#define HH 8
#define DK 8
#define CING 192
#define JJ 16384   // B*S*D = 256*64
#define PAD 68

// ---------------- scratch (__device__ globals) ----------------
__device__ __nv_bfloat16 g_AtH[NN * 1536];   // cols 0..767: At ; cols 768..1535: A2 (written by mode0)
__device__ __nv_bfloat16 g_AtL[NN * 1536];
__device__ __nv_bfloat16 g_SuH[NN * NN];     // support hi/lo (B operand of mode0)
__device__ __nv_bfloat16 g_SuL[NN * NN];
__device__ __nv_bfloat16 g_PkH[JJ * 1536];   // row j=bs*64+e: cols 0..767 = P1k^T, 768.. = P2k^T
__device__ __nv_bfloat16 g_PkL[JJ * 1536];
__device__ __nv_bfloat16 g_PvH[JJ * 1536];
__device__ __nv_bfloat16 g_PvL[JJ * 1536];
__device__ float g_Kf[NN * JJ];              // final projected K: [n][bs*64+e]
__device__ float g_Vf[NN * JJ];
__device__ float g_Qp[256 * NN * DD];        // projected+scaled Q: [(b*64+l)][n][e]
__device__ float g_WkG1[DD * CING];
__device__ float g_WvG2[DD * CING];
__device__ float g_bk2[DD];
__device__ float g_bv2[DD];

// ================= PTX helpers (vanilla compute_103) =================
__device__ __forceinline__ uint32_t smem_u32_of(const void* p) {
    uint32_t a;
    asm("{ .reg .u64 t; cvta.to.shared.u64 t, %1; cvt.u32.u64 %0, t; }" : "=r"(a) : "l"(p));
    return a;
}
__device__ __forceinline__ void ldm_x4(uint32_t& r0, uint32_t& r1, uint32_t& r2, uint32_t& r3,
                                       uint32_t addr) {
    asm volatile("ldmatrix.sync.aligned.m8n8.x4.shared.b16 {%0,%1,%2,%3}, [%4];"
                 : "=r"(r0), "=r"(r1), "=r"(r2), "=r"(r3) : "r"(addr));
}
__device__ __forceinline__ void mma_bf16(float* c, const uint32_t* a, const uint32_t* b) {
    asm volatile("mma.sync.aligned.m16n8k16.row.col.f32.bf16.bf16.f32 "
                 "{%0,%1,%2,%3}, {%4,%5,%6,%7}, {%8,%9}, {%0,%1,%2,%3};"
                 : "+f"(c[0]), "+f"(c[1]), "+f"(c[2]), "+f"(c[3])
                 : "r"(a[0]), "r"(a[1]), "r"(a[2]), "r"(a[3]), "r"(b[0]), "r"(b[1]));
}
__device__ __forceinline__ void cp16(uint32_t saddr, const void* g) {
    asm volatile("cp.async.cg.shared.global [%0], [%1], 16;" :: "r"(saddr), "l"(g));
}
#define CP_COMMIT() asm volatile("cp.async.commit_group;")
#define CP_WAIT0()  asm volatile("cp.async.wait_group 0;")

__device__ __forceinline__ void split4(float4 f, uint2& h, uint2& l) {
    __nv_bfloat162 h01 = __floats2bfloat162_rn(f.x, f.y);
    __nv_bfloat162 h23 = __floats2bfloat162_rn(f.z, f.w);
    float2 g01 = __bfloat1622float2(h01), g23 = __bfloat1622float2(h23);
    __nv_bfloat162 l01 = __floats2bfloat162_rn(f.x - g01.x, f.y - g01.y);
    __nv_bfloat162 l23 = __floats2bfloat162_rn(f.z - g23.x, f.w - g23.y);
    h = make_uint2(*(uint32_t*)&h01, *(uint32_t*)&h23);
    l = make_uint2(*(uint32_t*)&l01, *(uint32_t*)&l23);
}
__device__ __forceinline__ void split2_store(float c0, float c1,
                                             __nv_bfloat16* ph, __nv_bfloat16* pl) {
    __nv_bfloat162 h = __floats2bfloat162_rn(c0, c1);
    float2 hf = __bfloat1622float2(h);
    __nv_bfloat162 l = __floats2bfloat162_rn(c0 - hf.x, c1 - hf.y);
    *(uint32_t*)ph = *(uint32_t*)&h;
    *(uint32_t*)pl = *(uint32_t*)&l;
}

// ---------------- prep: At + support -> bf16 hi/lo ----------------
__global__ void prep_split_kernel(const float* __restrict__ a) {
    int idx = blockIdx.x * 256 + threadIdx.x;
    if (idx < NN * NN) {
        int n = idx / NN, v = idx - n * NN;
        float tv = a[v * NN + n];                    // At[n][v]
        __nv_bfloat16 h = __float2bfloat16(tv);
        g_AtH[n * 1536 + v] = h;
        g_AtL[n * 1536 + v] = __float2bfloat16(tv - __bfloat162float(h));
        float sv = a[idx];                           // support row-major
        h = __float2bfloat16(sv);
        g_SuH[idx] = h;
        g_SuL[idx] = __float2bfloat16(sv - __bfloat162float(h));
    }
}

// ---------------- prep: fold MLP weight into K/V projections ----------------
__global__ void prep_w_kernel(const float* __restrict__ Wk, const float* __restrict__ bk,
                              const float* __restrict__ Wg1, const float* __restrict__ bg1,
                              const float* __restrict__ Wv, const float* __restrict__ bv,
                              const float* __restrict__ Wg2, const float* __restrict__ bg2) {
    const float* W1 = blockIdx.x ? Wv : Wk;
    const float* Wg = blockIdx.x ? Wg2 : Wg1;
    const float* bg = blockIdx.x ? bg2 : bg1;
    const float* bb = blockIdx.x ? bv : bk;
    float* WG = blockIdx.x ? g_WvG2 : g_WkG1;
    float* b2 = blockIdx.x ? g_bv2 : g_bk2;

    __shared__ float sW[DD * DD];
    for (int i = threadIdx.x; i < DD * DD; i += 256) sW[i] = W1[i];
    __syncthreads();

    for (int idx = threadIdx.x; idx < DD * CING; idx += 256) {
        int e = idx / CING;
        int c = idx - e * CING;
        float s = 0.f;
        #pragma unroll 8
        for (int o = 0; o < DD; ++o) s += sW[e * DD + o] * Wg[o * CING + c];
        WG[idx] = s;
    }
    if (threadIdx.x < DD) {
        float s = 0.f;
        for (int o = 0; o < DD; ++o) s += sW[threadIdx.x * DD + o] * bg[o];
        b2[threadIdx.x] = s + bb[threadIdx.x];
    }
}

// =========================================================================
// proj kernel: per (ntile, bs, path) with X tile 128 rows x 64 ch.
//  pass a: C1[n][e] = X @ W0^T (+bias [,*scale]) -> output buffer (P0 term)
//  pass b (K/V only): C2[e'][n] = Wstack(W1;W2) @ X^T -> split bf16 into P buffers
// =========================================================================
#define PJ_XH 0
#define PJ_XL 18432
#define PJ_WH 36864
#define PJ_WL 64512
#define PROJ_SMEM 92160

__global__ __launch_bounds__(256) void proj_kernel(const float* __restrict__ keys,
                                                   const float* __restrict__ values,
                                                   const float* __restrict__ queries,
                                                   const float* __restrict__ Wq,
                                                   const float* __restrict__ bq) {
    extern __shared__ char smem[];
    const uint32_t smem_b = smem_u32_of(smem);
    const int tid = threadIdx.x, wid = tid >> 5, lane = tid & 31;
    const int warp_m = wid & 1, warp_n = wid >> 1;
    const int ntile = blockIdx.x;     // 0..5
    const int bs = blockIdx.y;        // 0..255
    const int path = blockIdx.z;      // 0 K, 1 V, 2 Q
    const int n0 = ntile * 128;

    const float* X = (path == 0) ? keys : (path == 1) ? values : queries;
    X += (long)bs * NN * DD;
    const float* WG = (path == 0) ? g_WkG1 : g_WvG2;

    // stage X (128 x 64) -> hi/lo bf16, 144B rows
    #pragma unroll
    for (int i = 0; i < 8; ++i) {
        int idx = tid + (i << 8);
        int r = idx >> 4, c4 = (idx & 15) << 2;
        float4 f = *(const float4*)(X + (long)(n0 + r) * DD + c4);
        uint2 h, l;
        split4(f, h, l);
        *(uint2*)(smem + PJ_XH + r * 144 + c4 * 2) = h;
        *(uint2*)(smem + PJ_XL + r * 144 + c4 * 2) = l;
    }
    // stage W (192 rows x 64) -> hi/lo
    #pragma unroll
    for (int i = 0; i < 12; ++i) {
        int idx = tid + (i << 8);
        int r = idx >> 4, c4 = (idx & 15) << 2;
        float4 f;
        if (path == 2) {
            f = (r < 64) ? *(const float4*)(Wq + r * DD + c4) : make_float4(0.f, 0.f, 0.f, 0.f);
        } else {
            int er = (r < 64) ? r : (r < 128 ? r - 64 : r - 128);
            int co = (r < 64) ? 0 : (r < 128 ? 64 : 128);
            f = *(const float4*)(WG + er * CING + co + c4);
        }
        uint2 h, l;
        split4(f, h, l);
        *(uint2*)(smem + PJ_WH + r * 144 + c4 * 2) = h;
        *(uint2*)(smem + PJ_WL + r * 144 + c4 * 2) = l;
    }
    __syncthreads();

    const int a_r = lane & 15, a_c = (lane >> 4) << 3;
    const int b_m = lane >> 3;
    const int b_n = (lane & 7) + ((b_m >> 1) << 3);
    const int b_k = (b_m & 1) << 3;
    const int g = lane >> 2, t = lane & 3;

    // ---- pass a: C1[n 128][e 64] = X @ W0^T ----
    {
        float acc[4][2][4] = {};
        const uint32_t abase = smem_b + (warp_m * 64 + a_r) * 144 + a_c * 2;
        const uint32_t bbase = smem_b + (warp_n * 16 + b_n) * 144 + b_k * 2;
        #pragma unroll
        for (int kc = 0; kc < 4; ++kc) {
            uint32_t kO = kc * 32;
            uint32_t ah[4][4], al_[4][4], bh[2][2], bl_[2][2];
            #pragma unroll
            for (int mi = 0; mi < 4; ++mi) {
                uint32_t ad = abase + mi * 2304 + kO;
                ldm_x4(ah[mi][0], ah[mi][1], ah[mi][2], ah[mi][3], ad + PJ_XH);
                ldm_x4(al_[mi][0], al_[mi][1], al_[mi][2], al_[mi][3], ad + PJ_XL);
            }
            ldm_x4(bh[0][0], bh[0][1], bh[1][0], bh[1][1], bbase + PJ_WH + kO);
            ldm_x4(bl_[0][0], bl_[0][1], bl_[1][0], bl_[1][1], bbase + PJ_WL + kO);
            #pragma unroll
            for (int mi = 0; mi < 4; ++mi)
                #pragma unroll
                for (int nj = 0; nj < 2; ++nj) {
                    mma_bf16(acc[mi][nj], ah[mi], bh[nj]);
                    mma_bf16(acc[mi][nj], ah[mi], bl_[nj]);
                    mma_bf16(acc[mi][nj], al_[mi], bh[nj]);
                }
        }
        #pragma unroll
        for (int mi = 0; mi < 4; ++mi)
            #pragma unroll
            for (int nj = 0; nj < 2; ++nj) {
                int nr = n0 + warp_m * 64 + mi * 16 + g;
                int e = warp_n * 16 + nj * 8 + t * 2;
                if (path == 2) {
                    const float sc = 0.35355339059327373f;
                    *(float2*)(g_Qp + ((long)bs * NN + nr) * DD + e) =
                        make_float2(acc[mi][nj][0] * sc + bq[e] * sc,
                                    acc[mi][nj][1] * sc + bq[e + 1] * sc);
                    *(float2*)(g_Qp + ((long)bs * NN + nr + 8) * DD + e) =
                        make_float2(acc[mi][nj][2] * sc + bq[e] * sc,
                                    acc[mi][nj][3] * sc + bq[e + 1] * sc);
                } else {
                    float* Cout = path ? g_Vf : g_Kf;
                    const float* bias = path ? g_bv2 : g_bk2;
                    *(float2*)(Cout + (long)nr * JJ + bs * 64 + e) =
                        make_float2(acc[mi][nj][0] + bias[e], acc[mi][nj][1] + bias[e + 1]);
                    *(float2*)(Cout + (long)(nr + 8) * JJ + bs * 64 + e) =
                        make_float2(acc[mi][nj][2] + bias[e], acc[mi][nj][3] + bias[e + 1]);
                }
            }
    }

    // ---- pass b: C2[e' 128][n 128] = Wstack @ X^T -> split store ----
    if (path < 2) {
        float acc[4][4][4] = {};
        const uint32_t abase = smem_b + (64 + warp_m * 64 + a_r) * 144 + a_c * 2;
        const uint32_t bbase = smem_b + (warp_n * 32 + b_n) * 144 + b_k * 2;
        #pragma unroll
        for (int kc = 0; kc < 4; ++kc) {
            uint32_t kO = kc * 32;
            uint32_t ah[4][4], al_[4][4], bh[4][2], bl_[4][2];
            #pragma unroll
            for (int mi = 0; mi < 4; ++mi) {
                uint32_t ad = abase + mi * 2304 + kO;
                ldm_x4(ah[mi][0], ah[mi][1], ah[mi][2], ah[mi][3], ad + PJ_WH);
                ldm_x4(al_[mi][0], al_[mi][1], al_[mi][2], al_[mi][3], ad + PJ_WL);
            }
            #pragma unroll
            for (int p = 0; p < 2; ++p) {
                uint32_t bd = bbase + p * 2304 + kO;
                ldm_x4(bh[2 * p][0], bh[2 * p][1], bh[2 * p + 1][0], bh[2 * p + 1][1], bd + PJ_XH);
                ldm_x4(bl_[2 * p][0], bl_[2 * p][1], bl_[2 * p + 1][0], bl_[2 * p + 1][1], bd + PJ_XL);
            }
            #pragma unroll
            for (int mi = 0; mi < 4; ++mi)
                #pragma unroll
                for (int nj = 0; nj < 4; ++nj) {
                    mma_bf16(acc[mi][nj], ah[mi], bh[nj]);
                    mma_bf16(acc[mi][nj], ah[mi], bl_[nj]);
                    mma_bf16(acc[mi][nj], al_[mi], bh[nj]);
                }
        }
        __nv_bfloat16* PH = path ? g_PvH : g_PkH;
        __nv_bfloat16* PL = path ? g_PvL : g_PkL;
        #pragma unroll
        for (int mi = 0; mi < 4; ++mi)
            #pragma unroll
            for (int nj = 0; nj < 4; ++nj) {
                int ep = warp_m * 64 + mi * 16 + g;
                int nl = n0 + warp_n * 32 + nj * 8 + t * 2;
                long row0 = (long)bs * 64 + (ep & 63);
                long col = (long)(ep >> 6) * 768 + nl;
                split2_store(acc[mi][nj][0], acc[mi][nj][1], PH + row0 * 1536 + col,
                             PL + row0 * 1536 + col);
                long row1 = (long)bs * 64 + ((ep + 8) & 63);
                split2_store(acc[mi][nj][2], acc[mi][nj][3], PH + row1 * 1536 + col,
                             PL + row1 * 1536 + col);
            }
    }
}

// =========================================================================
// big GEMM (cp.async, pre-split bf16), tile 256(M) x 128(N), Kc=64, 2-stage.
// 8 warps as 4(M) x 2(N); warp tile 64x64 (4 m-atoms x 8 n-atoms).
// mode 0: A2 = At @ support : grid (18,1), k=768, split-store -> g_AtH/L cols 768+
// mode 1: C += [At|A2] @ [P1;P2] : grid (384,2), k=1536, fp32 RMW epilogue
// blockIdx.x = ntile*3 + mtile (3 CTAs sharing a B strip are schedule-adjacent)
// =========================================================================
#define O_AH 0
#define O_AL 36864
#define O_BH 73728
#define O_BL 92160
#define STAGEB 110592
#define GEMM_SMEM (2 * STAGEB)   // 216 KB

__global__ __launch_bounds__(256, 1) void gemm_big_kernel(int mode) {
    extern __shared__ char smem[];
    const uint32_t smem_b = smem_u32_of(smem);
    const int tid = threadIdx.x, wid = tid >> 5, lane = tid & 31;
    const int warp_m = wid & 3;        // 4 M slabs of 64
    const int warp_n = wid >> 2;       // 2 N slabs of 64
    const int mtile = blockIdx.x % 3, ntile = blockIdx.x / 3;
    const int m0 = mtile * 256, j0 = ntile * 128;

    const __nv_bfloat16* Ah = g_AtH;
    const __nv_bfloat16* Al = g_AtL;
    const __nv_bfloat16 *Bh, *Bl;
    long sB;
    int ktiles;
    float* Cacc = nullptr;
    if (mode == 0) {
        Bh = g_SuH; Bl = g_SuL; sB = NN; ktiles = 12;
    } else {
        int p = blockIdx.y;
        Bh = p ? g_PvH : g_PkH;
        Bl = p ? g_PvL : g_PkL;
        sB = 1536; ktiles = 24;
        Cacc = p ? g_Vf : g_Kf;
    }
    const long sA = 1536;

    #define ISSUE_STAGE(kt)                                                      \
        {                                                                        \
            uint32_t st = smem_b + ((kt) & 1) * STAGEB;                          \
            long ko = (long)(kt) * 64;                                           \
            _Pragma("unroll")                                                    \
            for (int i = 0; i < 8; ++i) {                                        \
                int ch = tid + (i << 8);                                         \
                int r = ch >> 3, c = ch & 7;                                     \
                uint32_t so = st + r * 144 + c * 16;                             \
                cp16(so + O_AH, Ah + (long)(m0 + r) * sA + ko + c * 8);          \
                cp16(so + O_AL, Al + (long)(m0 + r) * sA + ko + c * 8);          \
            }                                                                    \
            _Pragma("unroll")                                                    \
            for (int i = 0; i < 4; ++i) {                                        \
                int ch = tid + (i << 8);                                         \
                int r = ch >> 3, c = ch & 7;                                     \
                uint32_t so = st + r * 144 + c * 16;                             \
                cp16(so + O_BH, Bh + (long)(j0 + r) * sB + ko + c * 8);          \
                cp16(so + O_BL, Bl + (long)(j0 + r) * sB + ko + c * 8);          \
            }                                                                    \
            CP_COMMIT();                                                         \
        }

    float acc[4][8][4] = {};   // [m-atom][n-atom][4]

    const int a_r = lane & 15, a_c = (lane >> 4) << 3;
    const int b_m = lane >> 3;
    const int b_n = (lane & 7) + ((b_m >> 1) << 3);
    const int b_k = (b_m & 1) << 3;
    const uint32_t a_base = (uint32_t)((warp_m * 64 + a_r) * 144 + a_c * 2);
    const uint32_t b_base = (uint32_t)((warp_n * 64 + b_n) * 144 + b_k * 2);

    ISSUE_STAGE(0);

    for (int kt = 0; kt < ktiles; ++kt) {
        CP_WAIT0();
        __syncthreads();
        if (kt + 1 < ktiles) ISSUE_STAGE(kt + 1);

        const uint32_t sbase = smem_b + (kt & 1) * STAGEB;
        #pragma unroll
        for (int kc = 0; kc < 4; ++kc) {
            const uint32_t kO = kc * 32;
            uint32_t bh[8][2], bl_[8][2];
            #pragma unroll
            for (int p = 0; p < 4; ++p) {
                uint32_t bd = sbase + b_base + p * 2304 + kO;
                ldm_x4(bh[2 * p][0], bh[2 * p][1], bh[2 * p + 1][0], bh[2 * p + 1][1], bd + O_BH);
                ldm_x4(bl_[2 * p][0], bl_[2 * p][1], bl_[2 * p + 1][0], bl_[2 * p + 1][1], bd + O_BL);
            }
            #pragma unroll
            for (int mi = 0; mi < 4; ++mi) {
                uint32_t ah[4], al_[4];
                uint32_t ad = sbase + a_base + mi * 2304 + kO;
                ldm_x4(ah[0], ah[1], ah[2], ah[3], ad + O_AH);
                ldm_x4(al_[0], al_[1], al_[2], al_[3], ad + O_AL);
                #pragma unroll
                for (int nj = 0; nj < 8; ++nj) {
                    mma_bf16(acc[mi][nj], ah, bh[nj]);
                    mma_bf16(acc[mi][nj], ah, bl_[nj]);
                    mma_bf16(acc[mi][nj], al_, bh[nj]);
                }
            }
        }
        __syncthreads();
    }

    // epilogue
    {
        const int g = lane >> 2, t = lane & 3;
        if (mode == 0) {
            #pragma unroll
            for (int mi = 0; mi < 4; ++mi) {
                int m = m0 + warp_m * 64 + mi * 16 + g;
                #pragma unroll
                for (int nj = 0; nj < 8; ++nj) {
                    int col = 768 + j0 + warp_n * 64 + nj * 8 + t * 2;
                    split2_store(acc[mi][nj][0], acc[mi][nj][1],
                                 g_AtH + (long)m * 1536 + col, g_AtL + (long)m * 1536 + col);
                    split2_store(acc[mi][nj][2], acc[mi][nj][3],
                                 g_AtH + (long)(m + 8) * 1536 + col, g_AtL + (long)(m + 8) * 1536 + col);
                }
            }
        } else {
            #pragma unroll
            for (int mi = 0; mi < 4; ++mi) {
                int m = m0 + warp_m * 64 + mi * 16 + g;
                #pragma unroll
                for (int nj = 0; nj < 8; ++nj) {
                    int col = j0 + warp_n * 64 + nj * 8 + t * 2;
                    float2 o0 = *(float2*)(Cacc + (long)m * JJ + col);
                    *(float2*)(Cacc + (long)m * JJ + col) =
                        make_float2(o0.x + acc[mi][nj][0], o0.y + acc[mi][nj][1]);
                    float2 o1 = *(float2*)(Cacc + (long)(m + 8) * JJ + col);
                    *(float2*)(Cacc + (long)(m + 8) * JJ + col) =
                        make_float2(o1.x + acc[mi][nj][2], o1.y + acc[mi][nj][3]);
                }
            }
        }
    }
    #undef ISSUE_STAGE
}

// ---------------- attn helpers ----------------
__device__ __forceinline__ void mm16(const float* __restrict__ sXt, const float* __restrict__ sWt,
                                     int tx, int ty, float acc[4][4]) {
    #pragma unroll 8
    for (int d = 0; d < 64; ++d) {
        float4 xv = *(const float4*)(sXt + d * PAD + ty * 4);
        float4 wv = *(const float4*)(sWt + d * PAD + tx * 4);
        float xs[4] = {xv.x, xv.y, xv.z, xv.w};
        float ws[4] = {wv.x, wv.y, wv.z, wv.w};
        #pragma unroll
        for (int i = 0; i < 4; ++i)
            #pragma unroll
            for (int j = 0; j < 4; ++j)
                acc[i][j] += xs[i] * ws[j];
    }
}
__device__ __forceinline__ void stage_xt(const float* __restrict__ src, long rowstride,
                                         float* __restrict__ dst, int tid) {
    #pragma unroll
    for (int it = 0; it < 4; ++it) {
        int idx = tid + it * 256;
        int r = idx >> 4;
        int c4 = (idx & 15) << 2;
        float4 f = *(const float4*)(src + (long)r * rowstride + c4);
        dst[(c4 + 0) * PAD + r] = f.x;
        dst[(c4 + 1) * PAD + r] = f.y;
        dst[(c4 + 2) * PAD + r] = f.z;
        dst[(c4 + 3) * PAD + r] = f.w;
    }
}

// ---------------- attention + output projection ----------------
__global__ __launch_bounds__(256) void attn_kernel(const float* __restrict__ Wo,
                                                   const float* __restrict__ bo,
                                                   float* __restrict__ out) {
    extern __shared__ float sm[];
    float* sXt = sm;                 // attn-out^T staging
    float* sWt = sm + 64 * PAD;
    float* sq = sm + 2 * 64 * PAD;
    float* sk = sm + 3 * 64 * PAD;
    float* sv = sm + 4 * 64 * PAD;

    const int n = blockIdx.x;
    const int b = blockIdx.y;
    const int tid = threadIdx.x;
    const int tx = tid & 15, ty = tid >> 4;

    // stage precomputed q/k/v
    #pragma unroll
    for (int i = 0; i < 4; ++i) {
        int idx = tid + (i << 8);
        int r = idx >> 4, c4 = (idx & 15) << 2;
        *(float4*)&sq[r * PAD + c4] = *(const float4*)(g_Qp + ((long)(b * 64 + r) * NN + n) * DD + c4);
        *(float4*)&sk[r * PAD + c4] = *(const float4*)(g_Kf + (long)n * JJ + b * 4096 + r * 64 + c4);
        *(float4*)&sv[r * PAD + c4] = *(const float4*)(g_Vf + (long)n * JJ + b * 4096 + r * 64 + c4);
    }
    stage_xt(Wo, DD, sWt, tid);
    __syncthreads();

    // attention: warp = head; lane handles query rows (lane, lane+32)
    {
        const int h = tid >> 5;
        const int lane = tid & 31;
        float qa[DK], qb[DK], aa[DK] = {}, ab[DK] = {};
        #pragma unroll
        for (int i = 0; i < DK; ++i) {
            qa[i] = sq[lane * PAD + h * DK + i];
            qb[i] = sq[(lane + 32) * PAD + h * DK + i];
        }
        float ma = -1e30f, mb = -1e30f, sa = 0.f, sb = 0.f;
        for (int s = 0; s < SS; ++s) {
            float da = 0.f, db = 0.f;
            #pragma unroll
            for (int i = 0; i < DK; ++i) {
                float kk = sk[s * PAD + h * DK + i];
                da += qa[i] * kk;
                db += qb[i] * kk;
            }
            float mna = fmaxf(ma, da), mnb = fmaxf(mb, db);
            float ca = __expf(ma - mna), pa = __expf(da - mna);
            float cb = __expf(mb - mnb), pb = __expf(db - mnb);
            sa = sa * ca + pa;
            sb = sb * cb + pb;
            ma = mna; mb = mnb;
            #pragma unroll
            for (int i = 0; i < DK; ++i) {
                float vv = sv[s * PAD + h * DK + i];
                aa[i] = aa[i] * ca + pa * vv;
                ab[i] = ab[i] * cb + pb * vv;
            }
        }
        float ra = 1.f / sa, rb = 1.f / sb;
        #pragma unroll
        for (int i = 0; i < DK; ++i) {
            sXt[(h * DK + i) * PAD + lane] = aa[i] * ra;
            sXt[(h * DK + i) * PAD + lane + 32] = ab[i] * rb;
        }
    }
    __syncthreads();

    // output projection
    {
        float acc[4][4] = {};
        mm16(sXt, sWt, tx, ty, acc);
        #pragma unroll
        for (int i = 0; i < 4; ++i) {
            int l = 4 * ty + i;
            float4 o = make_float4(acc[i][0] + bo[4 * tx + 0],
                                   acc[i][1] + bo[4 * tx + 1],
                                   acc[i][2] + bo[4 * tx + 2],
                                   acc[i][3] + bo[4 * tx + 3]);
            *(float4*)(out + ((long)(b * LL + l) * NN + n) * DD + 4 * tx) = o;
        }
    }
}

// ---------------- launch ----------------
extern "C" void kernel_launch(void* const* d_in, const int* in_sizes, int n_in,
                              void* d_out, int out_size) {
    const float* queries = (const float*)d_in[0];
    const float* keys    = (const float*)d_in[1];
    const float* values  = (const float*)d_in[2];
    const float* support = (const float*)d_in[3];
    const float* Wq = (const float*)d_in[4];
    const float* bq = (const float*)d_in[5];
    const float* Wk = (const float*)d_in[6];
    const float* bk = (const float*)d_in[7];
    const float* Wv = (const float*)d_in[8];
    const float* bv = (const float*)d_in[9];
    const float* Wo = (const float*)d_in[10];
    const float* bo = (const float*)d_in[11];
    const float* Wg1 = (const float*)d_in[12];
    const float* bg1 = (const float*)d_in[13];
    const float* Wg2 = (const float*)d_in[14];
    const float* bg2 = (const float*)d_in[15];
    float* out = (float*)d_out;

    cudaFuncSetAttribute(gemm_big_kernel, cudaFuncAttributeMaxDynamicSharedMemorySize, GEMM_SMEM);
    cudaFuncSetAttribute(proj_kernel, cudaFuncAttributeMaxDynamicSharedMemorySize, PROJ_SMEM);
    cudaFuncSetAttribute(attn_kernel, cudaFuncAttributeMaxDynamicSharedMemorySize,
                         5 * 64 * PAD * (int)sizeof(float));

    prep_split_kernel<<<2304, 256>>>(support);
    prep_w_kernel<<<2, 256>>>(Wk, bk, Wg1, bg1, Wv, bv, Wg2, bg2);

    // A2 = At @ support (split-stored into g_AtH/L cols 768+): 6 ntiles x 3 mtiles
    gemm_big_kernel<<<dim3(18, 1), 256, GEMM_SMEM>>>(0);
    // projections: P0 terms (+bias) into g_Kf/g_Vf/g_Qp, P1/P2 split into P buffers
    proj_kernel<<<dim3(6, 256, 3), 256, PROJ_SMEM>>>(keys, values, queries, Wq, bq);
    // diffusion: C += [At|A2] @ [P1;P2]   (128 ntiles x 3 mtiles, paths K/V)
    gemm_big_kernel<<<dim3(384, 2), 256, GEMM_SMEM>>>(1);

    const int smem = 5 * 64 * PAD * (int)sizeof(float);
    attn_kernel<<<dim3(NN, BB), 256, smem>>>(Wo, bo, out);
}

// round 8
// speedup vs baseline: 1.0505x; 1.0505x over previous
#include <cuda_runtime.h>
#include <cuda_bf16.h>
#include <cstdint>

// Problem constants
#define BB 4
#define LL 64
#define SS 64
#define NN 768
#define DD 64
#define HH 8
#define DK 8
#define CING 192
#define JJ 16384   // B*S*D = 256*64
#define PAD 68

// ---------------- scratch (__device__ globals) ----------------
__device__ __nv_bfloat16 g_AtH[NN * 1536];   // cols 0..767: At ; cols 768..1535: A2 (written by mode0)
__device__ __nv_bfloat16 g_AtL[NN * 1536];
__device__ __nv_bfloat16 g_SuH[NN * NN];     // support hi/lo (B operand of mode0)
__device__ __nv_bfloat16 g_SuL[NN * NN];
__device__ __nv_bfloat16 g_PkH[JJ * 1536];   // row j=bs*64+e: cols 0..767 = P1k^T, 768.. = P2k^T
__device__ __nv_bfloat16 g_PkL[JJ * 1536];
__device__ __nv_bfloat16 g_PvH[JJ * 1536];
__device__ __nv_bfloat16 g_PvL[JJ * 1536];
__device__ float g_Kf[NN * JJ];              // final projected K: [n][bs*64+e]
__device__ float g_Vf[NN * JJ];
__device__ float g_Qp[256 * NN * DD];        // projected+scaled Q: [(b*64+l)][n][e]
__device__ float g_WkG1[DD * CING];
__device__ float g_WvG2[DD * CING];
__device__ float g_bk2[DD];
__device__ float g_bv2[DD];

// ================= PTX helpers (vanilla compute_103) =================
__device__ __forceinline__ uint32_t smem_u32_of(const void* p) {
    uint32_t a;
    asm("{ .reg .u64 t; cvta.to.shared.u64 t, %1; cvt.u32.u64 %0, t; }" : "=r"(a) : "l"(p));
    return a;
}
__device__ __forceinline__ void ldm_x4(uint32_t& r0, uint32_t& r1, uint32_t& r2, uint32_t& r3,
                                       uint32_t addr) {
    asm volatile("ldmatrix.sync.aligned.m8n8.x4.shared.b16 {%0,%1,%2,%3}, [%4];"
                 : "=r"(r0), "=r"(r1), "=r"(r2), "=r"(r3) : "r"(addr));
}
__device__ __forceinline__ void mma_bf16(float* c, const uint32_t* a, const uint32_t* b) {
    asm volatile("mma.sync.aligned.m16n8k16.row.col.f32.bf16.bf16.f32 "
                 "{%0,%1,%2,%3}, {%4,%5,%6,%7}, {%8,%9}, {%0,%1,%2,%3};"
                 : "+f"(c[0]), "+f"(c[1]), "+f"(c[2]), "+f"(c[3])
                 : "r"(a[0]), "r"(a[1]), "r"(a[2]), "r"(a[3]), "r"(b[0]), "r"(b[1]));
}
__device__ __forceinline__ void cp16(uint32_t saddr, const void* g) {
    asm volatile("cp.async.cg.shared.global [%0], [%1], 16;" :: "r"(saddr), "l"(g));
}
#define CP_COMMIT() asm volatile("cp.async.commit_group;")
#define CP_WAIT0()  asm volatile("cp.async.wait_group 0;")
#define CP_WAIT1()  asm volatile("cp.async.wait_group 1;")

__device__ __forceinline__ void split4(float4 f, uint2& h, uint2& l) {
    __nv_bfloat162 h01 = __floats2bfloat162_rn(f.x, f.y);
    __nv_bfloat162 h23 = __floats2bfloat162_rn(f.z, f.w);
    float2 g01 = __bfloat1622float2(h01), g23 = __bfloat1622float2(h23);
    __nv_bfloat162 l01 = __floats2bfloat162_rn(f.x - g01.x, f.y - g01.y);
    __nv_bfloat162 l23 = __floats2bfloat162_rn(f.z - g23.x, f.w - g23.y);
    h = make_uint2(*(uint32_t*)&h01, *(uint32_t*)&h23);
    l = make_uint2(*(uint32_t*)&l01, *(uint32_t*)&l23);
}
__device__ __forceinline__ void split2_store(float c0, float c1,
                                             __nv_bfloat16* ph, __nv_bfloat16* pl) {
    __nv_bfloat162 h = __floats2bfloat162_rn(c0, c1);
    float2 hf = __bfloat1622float2(h);
    __nv_bfloat162 l = __floats2bfloat162_rn(c0 - hf.x, c1 - hf.y);
    *(uint32_t*)ph = *(uint32_t*)&h;
    *(uint32_t*)pl = *(uint32_t*)&l;
}

// ---------------- prep: At + support -> bf16 hi/lo ----------------
__global__ void prep_split_kernel(const float* __restrict__ a) {
    int idx = blockIdx.x * 256 + threadIdx.x;
    if (idx < NN * NN) {
        int n = idx / NN, v = idx - n * NN;
        float tv = a[v * NN + n];                    // At[n][v]
        __nv_bfloat16 h = __float2bfloat16(tv);
        g_AtH[n * 1536 + v] = h;
        g_AtL[n * 1536 + v] = __float2bfloat16(tv - __bfloat162float(h));
        float sv = a[idx];                           // support row-major
        h = __float2bfloat16(sv);
        g_SuH[idx] = h;
        g_SuL[idx] = __float2bfloat16(sv - __bfloat162float(h));
    }
}

// ---------------- prep: fold MLP weight into K/V projections ----------------
__global__ void prep_w_kernel(const float* __restrict__ Wk, const float* __restrict__ bk,
                              const float* __restrict__ Wg1, const float* __restrict__ bg1,
                              const float* __restrict__ Wv, const float* __restrict__ bv,
                              const float* __restrict__ Wg2, const float* __restrict__ bg2) {
    const float* W1 = blockIdx.x ? Wv : Wk;
    const float* Wg = blockIdx.x ? Wg2 : Wg1;
    const float* bg = blockIdx.x ? bg2 : bg1;
    const float* bb = blockIdx.x ? bv : bk;
    float* WG = blockIdx.x ? g_WvG2 : g_WkG1;
    float* b2 = blockIdx.x ? g_bv2 : g_bk2;

    __shared__ float sW[DD * DD];
    for (int i = threadIdx.x; i < DD * DD; i += 256) sW[i] = W1[i];
    __syncthreads();

    for (int idx = threadIdx.x; idx < DD * CING; idx += 256) {
        int e = idx / CING;
        int c = idx - e * CING;
        float s = 0.f;
        #pragma unroll 8
        for (int o = 0; o < DD; ++o) s += sW[e * DD + o] * Wg[o * CING + c];
        WG[idx] = s;
    }
    if (threadIdx.x < DD) {
        float s = 0.f;
        for (int o = 0; o < DD; ++o) s += sW[threadIdx.x * DD + o] * bg[o];
        b2[threadIdx.x] = s + bb[threadIdx.x];
    }
}

// =========================================================================
// proj kernel: per (ntile, bs, path) with X tile 128 rows x 64 ch.
//  pass a: C1[n][e] = X @ W0^T (+bias [,*scale]) -> output buffer (P0 term)
//  pass b (K/V only): C2[e'][n] = Wstack(W1;W2) @ X^T -> split bf16 into P buffers
// =========================================================================
#define PJ_XH 0
#define PJ_XL 18432
#define PJ_WH 36864
#define PJ_WL 64512
#define PROJ_SMEM 92160

__global__ __launch_bounds__(256) void proj_kernel(const float* __restrict__ keys,
                                                   const float* __restrict__ values,
                                                   const float* __restrict__ queries,
                                                   const float* __restrict__ Wq,
                                                   const float* __restrict__ bq) {
    extern __shared__ char smem[];
    const uint32_t smem_b = smem_u32_of(smem);
    const int tid = threadIdx.x, wid = tid >> 5, lane = tid & 31;
    const int warp_m = wid & 1, warp_n = wid >> 1;
    const int ntile = blockIdx.x;     // 0..5
    const int bs = blockIdx.y;        // 0..255
    const int path = blockIdx.z;      // 0 K, 1 V, 2 Q
    const int n0 = ntile * 128;

    const float* X = (path == 0) ? keys : (path == 1) ? values : queries;
    X += (long)bs * NN * DD;
    const float* WG = (path == 0) ? g_WkG1 : g_WvG2;

    // stage X (128 x 64) -> hi/lo bf16, 144B rows
    #pragma unroll
    for (int i = 0; i < 8; ++i) {
        int idx = tid + (i << 8);
        int r = idx >> 4, c4 = (idx & 15) << 2;
        float4 f = *(const float4*)(X + (long)(n0 + r) * DD + c4);
        uint2 h, l;
        split4(f, h, l);
        *(uint2*)(smem + PJ_XH + r * 144 + c4 * 2) = h;
        *(uint2*)(smem + PJ_XL + r * 144 + c4 * 2) = l;
    }
    // stage W (192 rows x 64) -> hi/lo
    #pragma unroll
    for (int i = 0; i < 12; ++i) {
        int idx = tid + (i << 8);
        int r = idx >> 4, c4 = (idx & 15) << 2;
        float4 f;
        if (path == 2) {
            f = (r < 64) ? *(const float4*)(Wq + r * DD + c4) : make_float4(0.f, 0.f, 0.f, 0.f);
        } else {
            int er = (r < 64) ? r : (r < 128 ? r - 64 : r - 128);
            int co = (r < 64) ? 0 : (r < 128 ? 64 : 128);
            f = *(const float4*)(WG + er * CING + co + c4);
        }
        uint2 h, l;
        split4(f, h, l);
        *(uint2*)(smem + PJ_WH + r * 144 + c4 * 2) = h;
        *(uint2*)(smem + PJ_WL + r * 144 + c4 * 2) = l;
    }
    __syncthreads();

    const int a_r = lane & 15, a_c = (lane >> 4) << 3;
    const int b_m = lane >> 3;
    const int b_n = (lane & 7) + ((b_m >> 1) << 3);
    const int b_k = (b_m & 1) << 3;
    const int g = lane >> 2, t = lane & 3;

    // ---- pass a: C1[n 128][e 64] = X @ W0^T ----
    {
        float acc[4][2][4] = {};
        const uint32_t abase = smem_b + (warp_m * 64 + a_r) * 144 + a_c * 2;
        const uint32_t bbase = smem_b + (warp_n * 16 + b_n) * 144 + b_k * 2;
        #pragma unroll
        for (int kc = 0; kc < 4; ++kc) {
            uint32_t kO = kc * 32;
            uint32_t ah[4][4], al_[4][4], bh[2][2], bl_[2][2];
            #pragma unroll
            for (int mi = 0; mi < 4; ++mi) {
                uint32_t ad = abase + mi * 2304 + kO;
                ldm_x4(ah[mi][0], ah[mi][1], ah[mi][2], ah[mi][3], ad + PJ_XH);
                ldm_x4(al_[mi][0], al_[mi][1], al_[mi][2], al_[mi][3], ad + PJ_XL);
            }
            ldm_x4(bh[0][0], bh[0][1], bh[1][0], bh[1][1], bbase + PJ_WH + kO);
            ldm_x4(bl_[0][0], bl_[0][1], bl_[1][0], bl_[1][1], bbase + PJ_WL + kO);
            #pragma unroll
            for (int mi = 0; mi < 4; ++mi)
                #pragma unroll
                for (int nj = 0; nj < 2; ++nj) {
                    mma_bf16(acc[mi][nj], ah[mi], bh[nj]);
                    mma_bf16(acc[mi][nj], ah[mi], bl_[nj]);
                    mma_bf16(acc[mi][nj], al_[mi], bh[nj]);
                }
        }
        #pragma unroll
        for (int mi = 0; mi < 4; ++mi)
            #pragma unroll
            for (int nj = 0; nj < 2; ++nj) {
                int nr = n0 + warp_m * 64 + mi * 16 + g;
                int e = warp_n * 16 + nj * 8 + t * 2;
                if (path == 2) {
                    const float sc = 0.35355339059327373f;
                    *(float2*)(g_Qp + ((long)bs * NN + nr) * DD + e) =
                        make_float2(acc[mi][nj][0] * sc + bq[e] * sc,
                                    acc[mi][nj][1] * sc + bq[e + 1] * sc);
                    *(float2*)(g_Qp + ((long)bs * NN + nr + 8) * DD + e) =
                        make_float2(acc[mi][nj][2] * sc + bq[e] * sc,
                                    acc[mi][nj][3] * sc + bq[e + 1] * sc);
                } else {
                    float* Cout = path ? g_Vf : g_Kf;
                    const float* bias = path ? g_bv2 : g_bk2;
                    *(float2*)(Cout + (long)nr * JJ + bs * 64 + e) =
                        make_float2(acc[mi][nj][0] + bias[e], acc[mi][nj][1] + bias[e + 1]);
                    *(float2*)(Cout + (long)(nr + 8) * JJ + bs * 64 + e) =
                        make_float2(acc[mi][nj][2] + bias[e], acc[mi][nj][3] + bias[e + 1]);
                }
            }
    }

    // ---- pass b: C2[e' 128][n 128] = Wstack @ X^T -> split store ----
    if (path < 2) {
        float acc[4][4][4] = {};
        const uint32_t abase = smem_b + (64 + warp_m * 64 + a_r) * 144 + a_c * 2;
        const uint32_t bbase = smem_b + (warp_n * 32 + b_n) * 144 + b_k * 2;
        #pragma unroll
        for (int kc = 0; kc < 4; ++kc) {
            uint32_t kO = kc * 32;
            uint32_t ah[4][4], al_[4][4], bh[4][2], bl_[4][2];
            #pragma unroll
            for (int mi = 0; mi < 4; ++mi) {
                uint32_t ad = abase + mi * 2304 + kO;
                ldm_x4(ah[mi][0], ah[mi][1], ah[mi][2], ah[mi][3], ad + PJ_WH);
                ldm_x4(al_[mi][0], al_[mi][1], al_[mi][2], al_[mi][3], ad + PJ_WL);
            }
            #pragma unroll
            for (int p = 0; p < 2; ++p) {
                uint32_t bd = bbase + p * 2304 + kO;
                ldm_x4(bh[2 * p][0], bh[2 * p][1], bh[2 * p + 1][0], bh[2 * p + 1][1], bd + PJ_XH);
                ldm_x4(bl_[2 * p][0], bl_[2 * p][1], bl_[2 * p + 1][0], bl_[2 * p + 1][1], bd + PJ_XL);
            }
            #pragma unroll
            for (int mi = 0; mi < 4; ++mi)
                #pragma unroll
                for (int nj = 0; nj < 4; ++nj) {
                    mma_bf16(acc[mi][nj], ah[mi], bh[nj]);
                    mma_bf16(acc[mi][nj], ah[mi], bl_[nj]);
                    mma_bf16(acc[mi][nj], al_[mi], bh[nj]);
                }
        }
        __nv_bfloat16* PH = path ? g_PvH : g_PkH;
        __nv_bfloat16* PL = path ? g_PvL : g_PkL;
        #pragma unroll
        for (int mi = 0; mi < 4; ++mi)
            #pragma unroll
            for (int nj = 0; nj < 4; ++nj) {
                int ep = warp_m * 64 + mi * 16 + g;
                int nl = n0 + warp_n * 32 + nj * 8 + t * 2;
                long row0 = (long)bs * 64 + (ep & 63);
                long col = (long)(ep >> 6) * 768 + nl;
                split2_store(acc[mi][nj][0], acc[mi][nj][1], PH + row0 * 1536 + col,
                             PL + row0 * 1536 + col);
                long row1 = (long)bs * 64 + ((ep + 8) & 63);
                split2_store(acc[mi][nj][2], acc[mi][nj][3], PH + row1 * 1536 + col,
                             PL + row1 * 1536 + col);
            }
    }
}

// =========================================================================
// big GEMM (cp.async, pre-split bf16), tile 128(M) x 128(N), Kc=64,
// 3 smem stages with 2 copies in flight (one __syncthreads per iteration).
// mode 0: A2 = At @ support : grid (36,1), k=768, split-store -> g_AtH/L cols 768+
// mode 1: C += [At|A2] @ [P1;P2] : grid (768,2), k=1536, fp32 RMW epilogue
// blockIdx.x = ntile*6 + mtile (6 CTAs sharing a B strip are schedule-adjacent)
// =========================================================================
#define O_AH 0
#define O_AL 18432
#define O_BH 36864
#define O_BL 55296
#define STAGEB 73728
#define GEMM_SMEM (3 * STAGEB)   // 216 KB

__global__ __launch_bounds__(256, 1) void gemm_big_kernel(int mode) {
    extern __shared__ char smem[];
    const uint32_t smem_b = smem_u32_of(smem);
    const int tid = threadIdx.x, wid = tid >> 5, lane = tid & 31;
    const int warp_m = wid & 1, warp_n = wid >> 1;
    const int mtile = blockIdx.x % 6, ntile = blockIdx.x / 6;
    const int m0 = mtile * 128, j0 = ntile * 128;

    const __nv_bfloat16* Ah = g_AtH;
    const __nv_bfloat16* Al = g_AtL;
    const __nv_bfloat16 *Bh, *Bl;
    long sB;
    int ktiles;
    float* Cacc = nullptr;
    if (mode == 0) {
        Bh = g_SuH; Bl = g_SuL; sB = NN; ktiles = 12;
    } else {
        int p = blockIdx.y;
        Bh = p ? g_PvH : g_PkH;
        Bl = p ? g_PvL : g_PkL;
        sB = 1536; ktiles = 24;
        Cacc = p ? g_Vf : g_Kf;
    }
    const long sA = 1536;

    #define ISSUE_STAGE(kt)                                                      \
        {                                                                        \
            uint32_t st = smem_b + ((kt) % 3) * STAGEB;                          \
            long ko = (long)(kt) * 64;                                           \
            _Pragma("unroll")                                                    \
            for (int i = 0; i < 4; ++i) {                                        \
                int ch = tid + (i << 8);                                         \
                int r = ch >> 3, c = ch & 7;                                     \
                uint32_t so = st + r * 144 + c * 16;                             \
                cp16(so + O_AH, Ah + (long)(m0 + r) * sA + ko + c * 8);          \
                cp16(so + O_AL, Al + (long)(m0 + r) * sA + ko + c * 8);          \
                cp16(so + O_BH, Bh + (long)(j0 + r) * sB + ko + c * 8);          \
                cp16(so + O_BL, Bl + (long)(j0 + r) * sB + ko + c * 8);          \
            }                                                                    \
            CP_COMMIT();                                                         \
        }

    float acc[4][4][4] = {};   // [m-atom][n-atom][4]

    const int a_r = lane & 15, a_c = (lane >> 4) << 3;
    const int b_m = lane >> 3;
    const int b_n = (lane & 7) + ((b_m >> 1) << 3);
    const int b_k = (b_m & 1) << 3;
    const uint32_t a_base = (uint32_t)((warp_m * 64 + a_r) * 144 + a_c * 2);
    const uint32_t b_base = (uint32_t)((warp_n * 32 + b_n) * 144 + b_k * 2);

    ISSUE_STAGE(0);
    if (ktiles > 1) ISSUE_STAGE(1);

    for (int kt = 0; kt < ktiles; ++kt) {
        if (kt + 1 < ktiles) CP_WAIT1(); else CP_WAIT0();
        __syncthreads();
        if (kt + 2 < ktiles) ISSUE_STAGE(kt + 2);

        const uint32_t sbase = smem_b + (kt % 3) * STAGEB;
        #pragma unroll
        for (int kc = 0; kc < 4; ++kc) {
            const uint32_t kO = kc * 32;
            uint32_t ah[4][4], al_[4][4], bh[4][2], bl_[4][2];
            #pragma unroll
            for (int mi = 0; mi < 4; ++mi) {
                uint32_t ad = sbase + a_base + mi * 2304 + kO;
                ldm_x4(ah[mi][0], ah[mi][1], ah[mi][2], ah[mi][3], ad + O_AH);
                ldm_x4(al_[mi][0], al_[mi][1], al_[mi][2], al_[mi][3], ad + O_AL);
            }
            #pragma unroll
            for (int p = 0; p < 2; ++p) {
                uint32_t bd = sbase + b_base + p * 2304 + kO;
                ldm_x4(bh[2 * p][0], bh[2 * p][1], bh[2 * p + 1][0], bh[2 * p + 1][1], bd + O_BH);
                ldm_x4(bl_[2 * p][0], bl_[2 * p][1], bl_[2 * p + 1][0], bl_[2 * p + 1][1], bd + O_BL);
            }
            #pragma unroll
            for (int mi = 0; mi < 4; ++mi)
                #pragma unroll
                for (int nj = 0; nj < 4; ++nj) {
                    mma_bf16(acc[mi][nj], ah[mi], bh[nj]);
                    mma_bf16(acc[mi][nj], ah[mi], bl_[nj]);
                    mma_bf16(acc[mi][nj], al_[mi], bh[nj]);
                }
        }
    }

    // epilogue (all copies drained; mainloop ended with compute on last stage)
    __syncthreads();
    {
        const int g = lane >> 2, t = lane & 3;
        if (mode == 0) {
            #pragma unroll
            for (int mi = 0; mi < 4; ++mi) {
                int m = m0 + warp_m * 64 + mi * 16 + g;
                #pragma unroll
                for (int nj = 0; nj < 4; ++nj) {
                    int col = 768 + j0 + warp_n * 32 + nj * 8 + t * 2;
                    split2_store(acc[mi][nj][0], acc[mi][nj][1],
                                 g_AtH + (long)m * 1536 + col, g_AtL + (long)m * 1536 + col);
                    split2_store(acc[mi][nj][2], acc[mi][nj][3],
                                 g_AtH + (long)(m + 8) * 1536 + col, g_AtL + (long)(m + 8) * 1536 + col);
                }
            }
        } else {
            #pragma unroll
            for (int mi = 0; mi < 4; ++mi) {
                int m = m0 + warp_m * 64 + mi * 16 + g;
                #pragma unroll
                for (int nj = 0; nj < 4; ++nj) {
                    int col = j0 + warp_n * 32 + nj * 8 + t * 2;
                    float2 o0 = *(float2*)(Cacc + (long)m * JJ + col);
                    *(float2*)(Cacc + (long)m * JJ + col) =
                        make_float2(o0.x + acc[mi][nj][0], o0.y + acc[mi][nj][1]);
                    float2 o1 = *(float2*)(Cacc + (long)(m + 8) * JJ + col);
                    *(float2*)(Cacc + (long)(m + 8) * JJ + col) =
                        make_float2(o1.x + acc[mi][nj][2], o1.y + acc[mi][nj][3]);
                }
            }
        }
    }
    #undef ISSUE_STAGE
}

// ---------------- attn helpers ----------------
__device__ __forceinline__ void mm16(const float* __restrict__ sXt, const float* __restrict__ sWt,
                                     int tx, int ty, float acc[4][4]) {
    #pragma unroll 8
    for (int d = 0; d < 64; ++d) {
        float4 xv = *(const float4*)(sXt + d * PAD + ty * 4);
        float4 wv = *(const float4*)(sWt + d * PAD + tx * 4);
        float xs[4] = {xv.x, xv.y, xv.z, xv.w};
        float ws[4] = {wv.x, wv.y, wv.z, wv.w};
        #pragma unroll
        for (int i = 0; i < 4; ++i)
            #pragma unroll
            for (int j = 0; j < 4; ++j)
                acc[i][j] += xs[i] * ws[j];
    }
}
__device__ __forceinline__ void stage_xt(const float* __restrict__ src, long rowstride,
                                         float* __restrict__ dst, int tid) {
    #pragma unroll
    for (int it = 0; it < 4; ++it) {
        int idx = tid + it * 256;
        int r = idx >> 4;
        int c4 = (idx & 15) << 2;
        float4 f = *(const float4*)(src + (long)r * rowstride + c4);
        dst[(c4 + 0) * PAD + r] = f.x;
        dst[(c4 + 1) * PAD + r] = f.y;
        dst[(c4 + 2) * PAD + r] = f.z;
        dst[(c4 + 3) * PAD + r] = f.w;
    }
}

// ---------------- attention + output projection ----------------
__global__ __launch_bounds__(256) void attn_kernel(const float* __restrict__ Wo,
                                                   const float* __restrict__ bo,
                                                   float* __restrict__ out) {
    extern __shared__ float sm[];
    float* sXt = sm;                 // attn-out^T staging
    float* sWt = sm + 64 * PAD;
    float* sq = sm + 2 * 64 * PAD;
    float* sk = sm + 3 * 64 * PAD;
    float* sv = sm + 4 * 64 * PAD;

    const int n = blockIdx.x;
    const int b = blockIdx.y;
    const int tid = threadIdx.x;
    const int tx = tid & 15, ty = tid >> 4;

    // stage precomputed q/k/v
    #pragma unroll
    for (int i = 0; i < 4; ++i) {
        int idx = tid + (i << 8);
        int r = idx >> 4, c4 = (idx & 15) << 2;
        *(float4*)&sq[r * PAD + c4] = *(const float4*)(g_Qp + ((long)(b * 64 + r) * NN + n) * DD + c4);
        *(float4*)&sk[r * PAD + c4] = *(const float4*)(g_Kf + (long)n * JJ + b * 4096 + r * 64 + c4);
        *(float4*)&sv[r * PAD + c4] = *(const float4*)(g_Vf + (long)n * JJ + b * 4096 + r * 64 + c4);
    }
    stage_xt(Wo, DD, sWt, tid);
    __syncthreads();

    // attention: warp = head; lane handles query rows (lane, lane+32)
    {
        const int h = tid >> 5;
        const int lane = tid & 31;
        float qa[DK], qb[DK], aa[DK] = {}, ab[DK] = {};
        #pragma unroll
        for (int i = 0; i < DK; ++i) {
            qa[i] = sq[lane * PAD + h * DK + i];
            qb[i] = sq[(lane + 32) * PAD + h * DK + i];
        }
        float ma = -1e30f, mb = -1e30f, sa = 0.f, sb = 0.f;
        for (int s = 0; s < SS; ++s) {
            float da = 0.f, db = 0.f;
            #pragma unroll
            for (int i = 0; i < DK; ++i) {
                float kk = sk[s * PAD + h * DK + i];
                da += qa[i] * kk;
                db += qb[i] * kk;
            }
            float mna = fmaxf(ma, da), mnb = fmaxf(mb, db);
            float ca = __expf(ma - mna), pa = __expf(da - mna);
            float cb = __expf(mb - mnb), pb = __expf(db - mnb);
            sa = sa * ca + pa;
            sb = sb * cb + pb;
            ma = mna; mb = mnb;
            #pragma unroll
            for (int i = 0; i < DK; ++i) {
                float vv = sv[s * PAD + h * DK + i];
                aa[i] = aa[i] * ca + pa * vv;
                ab[i] = ab[i] * cb + pb * vv;
            }
        }
        float ra = 1.f / sa, rb = 1.f / sb;
        #pragma unroll
        for (int i = 0; i < DK; ++i) {
            sXt[(h * DK + i) * PAD + lane] = aa[i] * ra;
            sXt[(h * DK + i) * PAD + lane + 32] = ab[i] * rb;
        }
    }
    __syncthreads();

    // output projection
    {
        float acc[4][4] = {};
        mm16(sXt, sWt, tx, ty, acc);
        #pragma unroll
        for (int i = 0; i < 4; ++i) {
            int l = 4 * ty + i;
            float4 o = make_float4(acc[i][0] + bo[4 * tx + 0],
                                   acc[i][1] + bo[4 * tx + 1],
                                   acc[i][2] + bo[4 * tx + 2],
                                   acc[i][3] + bo[4 * tx + 3]);
            *(float4*)(out + ((long)(b * LL + l) * NN + n) * DD + 4 * tx) = o;
        }
    }
}

// ---------------- launch ----------------
extern "C" void kernel_launch(void* const* d_in, const int* in_sizes, int n_in,
                              void* d_out, int out_size) {
    const float* queries = (const float*)d_in[0];
    const float* keys    = (const float*)d_in[1];
    const float* values  = (const float*)d_in[2];
    const float* support = (const float*)d_in[3];
    const float* Wq = (const float*)d_in[4];
    const float* bq = (const float*)d_in[5];
    const float* Wk = (const float*)d_in[6];
    const float* bk = (const float*)d_in[7];
    const float* Wv = (const float*)d_in[8];
    const float* bv = (const float*)d_in[9];
    const float* Wo = (const float*)d_in[10];
    const float* bo = (const float*)d_in[11];
    const float* Wg1 = (const float*)d_in[12];
    const float* bg1 = (const float*)d_in[13];
    const float* Wg2 = (const float*)d_in[14];
    const float* bg2 = (const float*)d_in[15];
    float* out = (float*)d_out;

    cudaFuncSetAttribute(gemm_big_kernel, cudaFuncAttributeMaxDynamicSharedMemorySize, GEMM_SMEM);
    cudaFuncSetAttribute(proj_kernel, cudaFuncAttributeMaxDynamicSharedMemorySize, PROJ_SMEM);
    cudaFuncSetAttribute(attn_kernel, cudaFuncAttributeMaxDynamicSharedMemorySize,
                         5 * 64 * PAD * (int)sizeof(float));

    prep_split_kernel<<<2304, 256>>>(support);
    prep_w_kernel<<<2, 256>>>(Wk, bk, Wg1, bg1, Wv, bv, Wg2, bg2);

    // A2 = At @ support (split-stored into g_AtH/L cols 768+): 6 ntiles x 6 mtiles
    gemm_big_kernel<<<dim3(36, 1), 256, GEMM_SMEM>>>(0);
    // projections: P0 terms (+bias) into g_Kf/g_Vf/g_Qp, P1/P2 split into P buffers
    proj_kernel<<<dim3(6, 256, 3), 256, PROJ_SMEM>>>(keys, values, queries, Wq, bq);
    // diffusion: C += [At|A2] @ [P1;P2]   (128 ntiles x 6 mtiles, paths K/V)
    gemm_big_kernel<<<dim3(768, 2), 256, GEMM_SMEM>>>(1);

    const int smem = 5 * 64 * PAD * (int)sizeof(float);
    attn_kernel<<<dim3(NN, BB), 256, smem>>>(Wo, bo, out);
}

// round 9
// speedup vs baseline: 1.9641x; 1.8697x over previous
#include <cuda_runtime.h>
#include <cuda_fp16.h>
#include <cstdint>

// Problem constants
#define BB 4
#define LL 64
#define SS 64
#define NN 768
#define DD 64
#define HH 8
#define DK 8
#define CING 192
#define JJ 16384   // B*S*D = 256*64
#define PAD 68

// ---------------- scratch (__device__ globals) ----------------
__device__ __half g_At16[NN * 1536];   // cols 0..767: At ; cols 768..1535: A2 (written by mode0)
__device__ __half g_Su16[NN * NN];     // support (B operand of mode0)
__device__ __half g_Pk[JJ * 1536];     // row j=bs*64+e: cols 0..767 = P1k^T, 768.. = P2k^T
__device__ __half g_Pv[JJ * 1536];
__device__ float g_Kf[NN * JJ];        // final projected K: [n][bs*64+e]
__device__ float g_Vf[NN * JJ];
__device__ float g_Qp[256 * NN * DD];  // projected+scaled Q: [(b*64+l)][n][e]
__device__ float g_WkG1[DD * CING];
__device__ float g_WvG2[DD * CING];
__device__ float g_bk2[DD];
__device__ float g_bv2[DD];

// ================= PTX helpers (vanilla compute_103) =================
__device__ __forceinline__ uint32_t smem_u32_of(const void* p) {
    uint32_t a;
    asm("{ .reg .u64 t; cvta.to.shared.u64 t, %1; cvt.u32.u64 %0, t; }" : "=r"(a) : "l"(p));
    return a;
}
__device__ __forceinline__ void ldm_x4(uint32_t& r0, uint32_t& r1, uint32_t& r2, uint32_t& r3,
                                       uint32_t addr) {
    asm volatile("ldmatrix.sync.aligned.m8n8.x4.shared.b16 {%0,%1,%2,%3}, [%4];"
                 : "=r"(r0), "=r"(r1), "=r"(r2), "=r"(r3) : "r"(addr));
}
__device__ __forceinline__ void mma_f16(float* c, const uint32_t* a, const uint32_t* b) {
    asm volatile("mma.sync.aligned.m16n8k16.row.col.f32.f16.f16.f32 "
                 "{%0,%1,%2,%3}, {%4,%5,%6,%7}, {%8,%9}, {%0,%1,%2,%3};"
                 : "+f"(c[0]), "+f"(c[1]), "+f"(c[2]), "+f"(c[3])
                 : "r"(a[0]), "r"(a[1]), "r"(a[2]), "r"(a[3]), "r"(b[0]), "r"(b[1]));
}
__device__ __forceinline__ void cp16(uint32_t saddr, const void* g) {
    asm volatile("cp.async.cg.shared.global [%0], [%1], 16;" :: "r"(saddr), "l"(g));
}
#define CP_COMMIT() asm volatile("cp.async.commit_group;")
#define CP_WAIT0()  asm volatile("cp.async.wait_group 0;")
#define CP_WAIT1()  asm volatile("cp.async.wait_group 1;")

__device__ __forceinline__ uint2 h4_of(float4 f) {
    __half2 a = __floats2half2_rn(f.x, f.y);
    __half2 b = __floats2half2_rn(f.z, f.w);
    return make_uint2(*(uint32_t*)&a, *(uint32_t*)&b);
}

// ---------------- prep: At + support -> fp16 ----------------
__global__ void prep_split_kernel(const float* __restrict__ a) {
    int idx = blockIdx.x * 256 + threadIdx.x;
    if (idx < NN * NN) {
        int n = idx / NN, v = idx - n * NN;
        g_At16[n * 1536 + v] = __float2half(a[v * NN + n]);   // At[n][v]
        g_Su16[idx] = __float2half(a[idx]);                   // support row-major
    }
}

// ---------------- prep: fold MLP weight into K/V projections ----------------
__global__ void prep_w_kernel(const float* __restrict__ Wk, const float* __restrict__ bk,
                              const float* __restrict__ Wg1, const float* __restrict__ bg1,
                              const float* __restrict__ Wv, const float* __restrict__ bv,
                              const float* __restrict__ Wg2, const float* __restrict__ bg2) {
    const float* W1 = blockIdx.x ? Wv : Wk;
    const float* Wg = blockIdx.x ? Wg2 : Wg1;
    const float* bg = blockIdx.x ? bg2 : bg1;
    const float* bb = blockIdx.x ? bv : bk;
    float* WG = blockIdx.x ? g_WvG2 : g_WkG1;
    float* b2 = blockIdx.x ? g_bv2 : g_bk2;

    __shared__ float sW[DD * DD];
    for (int i = threadIdx.x; i < DD * DD; i += 256) sW[i] = W1[i];
    __syncthreads();

    for (int idx = threadIdx.x; idx < DD * CING; idx += 256) {
        int e = idx / CING;
        int c = idx - e * CING;
        float s = 0.f;
        #pragma unroll 8
        for (int o = 0; o < DD; ++o) s += sW[e * DD + o] * Wg[o * CING + c];
        WG[idx] = s;
    }
    if (threadIdx.x < DD) {
        float s = 0.f;
        for (int o = 0; o < DD; ++o) s += sW[threadIdx.x * DD + o] * bg[o];
        b2[threadIdx.x] = s + bb[threadIdx.x];
    }
}

// =========================================================================
// proj kernel: per (ntile, bs, path) with X tile 128 rows x 64 ch (fp16 MMA).
//  pass a: C1[n][e] = X @ W0^T (+bias [,*scale]) -> output buffer (P0 term)
//  pass b (K/V only): C2[e'][n] = Wstack(W1;W2) @ X^T -> fp16 into P buffers
// =========================================================================
#define PJ_X 0
#define PJ_W 18432
#define PROJ_SMEM 46080

__global__ __launch_bounds__(256) void proj_kernel(const float* __restrict__ keys,
                                                   const float* __restrict__ values,
                                                   const float* __restrict__ queries,
                                                   const float* __restrict__ Wq,
                                                   const float* __restrict__ bq) {
    extern __shared__ char smem[];
    const uint32_t smem_b = smem_u32_of(smem);
    const int tid = threadIdx.x, wid = tid >> 5, lane = tid & 31;
    const int warp_m = wid & 1, warp_n = wid >> 1;
    const int ntile = blockIdx.x;     // 0..5
    const int bs = blockIdx.y;        // 0..255
    const int path = blockIdx.z;      // 0 K, 1 V, 2 Q
    const int n0 = ntile * 128;

    const float* X = (path == 0) ? keys : (path == 1) ? values : queries;
    X += (long)bs * NN * DD;
    const float* WG = (path == 0) ? g_WkG1 : g_WvG2;

    // stage X (128 x 64) -> fp16, 144B rows
    #pragma unroll
    for (int i = 0; i < 8; ++i) {
        int idx = tid + (i << 8);
        int r = idx >> 4, c4 = (idx & 15) << 2;
        float4 f = *(const float4*)(X + (long)(n0 + r) * DD + c4);
        *(uint2*)(smem + PJ_X + r * 144 + c4 * 2) = h4_of(f);
    }
    // stage W (192 rows x 64) -> fp16
    #pragma unroll
    for (int i = 0; i < 12; ++i) {
        int idx = tid + (i << 8);
        int r = idx >> 4, c4 = (idx & 15) << 2;
        float4 f;
        if (path == 2) {
            f = (r < 64) ? *(const float4*)(Wq + r * DD + c4) : make_float4(0.f, 0.f, 0.f, 0.f);
        } else {
            int er = (r < 64) ? r : (r < 128 ? r - 64 : r - 128);
            int co = (r < 64) ? 0 : (r < 128 ? 64 : 128);
            f = *(const float4*)(WG + er * CING + co + c4);
        }
        *(uint2*)(smem + PJ_W + r * 144 + c4 * 2) = h4_of(f);
    }
    __syncthreads();

    const int a_r = lane & 15, a_c = (lane >> 4) << 3;
    const int b_m = lane >> 3;
    const int b_n = (lane & 7) + ((b_m >> 1) << 3);
    const int b_k = (b_m & 1) << 3;
    const int g = lane >> 2, t = lane & 3;

    // ---- pass a: C1[n 128][e 64] = X @ W0^T ----
    {
        float acc[4][2][4] = {};
        const uint32_t abase = smem_b + (warp_m * 64 + a_r) * 144 + a_c * 2;
        const uint32_t bbase = smem_b + (warp_n * 16 + b_n) * 144 + b_k * 2;
        #pragma unroll
        for (int kc = 0; kc < 4; ++kc) {
            uint32_t kO = kc * 32;
            uint32_t ah[4][4], bh[2][2];
            #pragma unroll
            for (int mi = 0; mi < 4; ++mi) {
                uint32_t ad = abase + mi * 2304 + kO;
                ldm_x4(ah[mi][0], ah[mi][1], ah[mi][2], ah[mi][3], ad + PJ_X);
            }
            ldm_x4(bh[0][0], bh[0][1], bh[1][0], bh[1][1], bbase + PJ_W + kO);
            #pragma unroll
            for (int mi = 0; mi < 4; ++mi)
                #pragma unroll
                for (int nj = 0; nj < 2; ++nj)
                    mma_f16(acc[mi][nj], ah[mi], bh[nj]);
        }
        #pragma unroll
        for (int mi = 0; mi < 4; ++mi)
            #pragma unroll
            for (int nj = 0; nj < 2; ++nj) {
                int nr = n0 + warp_m * 64 + mi * 16 + g;
                int e = warp_n * 16 + nj * 8 + t * 2;
                if (path == 2) {
                    const float sc = 0.35355339059327373f;
                    *(float2*)(g_Qp + ((long)bs * NN + nr) * DD + e) =
                        make_float2(acc[mi][nj][0] * sc + bq[e] * sc,
                                    acc[mi][nj][1] * sc + bq[e + 1] * sc);
                    *(float2*)(g_Qp + ((long)bs * NN + nr + 8) * DD + e) =
                        make_float2(acc[mi][nj][2] * sc + bq[e] * sc,
                                    acc[mi][nj][3] * sc + bq[e + 1] * sc);
                } else {
                    float* Cout = path ? g_Vf : g_Kf;
                    const float* bias = path ? g_bv2 : g_bk2;
                    *(float2*)(Cout + (long)nr * JJ + bs * 64 + e) =
                        make_float2(acc[mi][nj][0] + bias[e], acc[mi][nj][1] + bias[e + 1]);
                    *(float2*)(Cout + (long)(nr + 8) * JJ + bs * 64 + e) =
                        make_float2(acc[mi][nj][2] + bias[e], acc[mi][nj][3] + bias[e + 1]);
                }
            }
    }

    // ---- pass b: C2[e' 128][n 128] = Wstack @ X^T -> fp16 store ----
    if (path < 2) {
        float acc[4][4][4] = {};
        const uint32_t abase = smem_b + (64 + warp_m * 64 + a_r) * 144 + a_c * 2;
        const uint32_t bbase = smem_b + (warp_n * 32 + b_n) * 144 + b_k * 2;
        #pragma unroll
        for (int kc = 0; kc < 4; ++kc) {
            uint32_t kO = kc * 32;
            uint32_t ah[4][4], bh[4][2];
            #pragma unroll
            for (int mi = 0; mi < 4; ++mi) {
                uint32_t ad = abase + mi * 2304 + kO;
                ldm_x4(ah[mi][0], ah[mi][1], ah[mi][2], ah[mi][3], ad + PJ_W);
            }
            #pragma unroll
            for (int p = 0; p < 2; ++p) {
                uint32_t bd = bbase + p * 2304 + kO;
                ldm_x4(bh[2 * p][0], bh[2 * p][1], bh[2 * p + 1][0], bh[2 * p + 1][1], bd + PJ_X);
            }
            #pragma unroll
            for (int mi = 0; mi < 4; ++mi)
                #pragma unroll
                for (int nj = 0; nj < 4; ++nj)
                    mma_f16(acc[mi][nj], ah[mi], bh[nj]);
        }
        __half* P = path ? g_Pv : g_Pk;
        #pragma unroll
        for (int mi = 0; mi < 4; ++mi)
            #pragma unroll
            for (int nj = 0; nj < 4; ++nj) {
                int ep = warp_m * 64 + mi * 16 + g;
                int nl = n0 + warp_n * 32 + nj * 8 + t * 2;
                long row0 = (long)bs * 64 + (ep & 63);
                long col = (long)(ep >> 6) * 768 + nl;
                *(__half2*)(P + row0 * 1536 + col) = __floats2half2_rn(acc[mi][nj][0], acc[mi][nj][1]);
                long row1 = (long)bs * 64 + ((ep + 8) & 63);
                *(__half2*)(P + row1 * 1536 + col) = __floats2half2_rn(acc[mi][nj][2], acc[mi][nj][3]);
            }
    }
}

// =========================================================================
// big GEMM (cp.async, fp16), tile 128(M) x 128(N), Kc=64,
// 3 smem stages with 2 copies in flight, 2 CTAs/SM.
// mode 0: A2 = At @ support : grid (36,1), k=768, fp16 store -> g_At16 cols 768+
// mode 1: C += [At|A2] @ [P1;P2] : grid (768,2), k=1536, fp32 RMW epilogue
// blockIdx.x = ntile*6 + mtile (6 CTAs sharing a B strip are schedule-adjacent)
// =========================================================================
#define O_A 0
#define O_B 18432
#define STAGEB 36864
#define GEMM_SMEM (3 * STAGEB)   // 108 KB -> 2 CTAs/SM

__global__ __launch_bounds__(256, 2) void gemm_big_kernel(int mode) {
    extern __shared__ char smem[];
    const uint32_t smem_b = smem_u32_of(smem);
    const int tid = threadIdx.x, wid = tid >> 5, lane = tid & 31;
    const int warp_m = wid & 1, warp_n = wid >> 1;
    const int mtile = blockIdx.x % 6, ntile = blockIdx.x / 6;
    const int m0 = mtile * 128, j0 = ntile * 128;

    const __half* Ap = g_At16;
    const __half* Bp;
    long sB;
    int ktiles;
    float* Cacc = nullptr;
    if (mode == 0) {
        Bp = g_Su16; sB = NN; ktiles = 12;
    } else {
        int p = blockIdx.y;
        Bp = p ? g_Pv : g_Pk;
        sB = 1536; ktiles = 24;
        Cacc = p ? g_Vf : g_Kf;
    }
    const long sA = 1536;

    #define ISSUE_STAGE(kt)                                                      \
        {                                                                        \
            uint32_t st = smem_b + ((kt) % 3) * STAGEB;                          \
            long ko = (long)(kt) * 64;                                           \
            _Pragma("unroll")                                                    \
            for (int i = 0; i < 4; ++i) {                                        \
                int ch = tid + (i << 8);                                         \
                int r = ch >> 3, c = ch & 7;                                     \
                uint32_t so = st + r * 144 + c * 16;                             \
                cp16(so + O_A, Ap + (long)(m0 + r) * sA + ko + c * 8);           \
                cp16(so + O_B, Bp + (long)(j0 + r) * sB + ko + c * 8);           \
            }                                                                    \
            CP_COMMIT();                                                         \
        }

    float acc[4][4][4] = {};   // [m-atom][n-atom][4]

    const int a_r = lane & 15, a_c = (lane >> 4) << 3;
    const int b_m = lane >> 3;
    const int b_n = (lane & 7) + ((b_m >> 1) << 3);
    const int b_k = (b_m & 1) << 3;
    const uint32_t a_base = (uint32_t)((warp_m * 64 + a_r) * 144 + a_c * 2);
    const uint32_t b_base = (uint32_t)((warp_n * 32 + b_n) * 144 + b_k * 2);

    ISSUE_STAGE(0);
    if (ktiles > 1) ISSUE_STAGE(1);

    for (int kt = 0; kt < ktiles; ++kt) {
        if (kt + 1 < ktiles) CP_WAIT1(); else CP_WAIT0();
        __syncthreads();
        if (kt + 2 < ktiles) ISSUE_STAGE(kt + 2);

        const uint32_t sbase = smem_b + (kt % 3) * STAGEB;
        #pragma unroll
        for (int kc = 0; kc < 4; ++kc) {
            const uint32_t kO = kc * 32;
            uint32_t ah[4][4], bh[4][2];
            #pragma unroll
            for (int mi = 0; mi < 4; ++mi) {
                uint32_t ad = sbase + a_base + mi * 2304 + kO;
                ldm_x4(ah[mi][0], ah[mi][1], ah[mi][2], ah[mi][3], ad + O_A);
            }
            #pragma unroll
            for (int p = 0; p < 2; ++p) {
                uint32_t bd = sbase + b_base + p * 2304 + kO;
                ldm_x4(bh[2 * p][0], bh[2 * p][1], bh[2 * p + 1][0], bh[2 * p + 1][1], bd + O_B);
            }
            #pragma unroll
            for (int mi = 0; mi < 4; ++mi)
                #pragma unroll
                for (int nj = 0; nj < 4; ++nj)
                    mma_f16(acc[mi][nj], ah[mi], bh[nj]);
        }
    }

    // epilogue (all copies drained; mainloop ended with compute on last stage)
    __syncthreads();
    {
        const int g = lane >> 2, t = lane & 3;
        if (mode == 0) {
            #pragma unroll
            for (int mi = 0; mi < 4; ++mi) {
                int m = m0 + warp_m * 64 + mi * 16 + g;
                #pragma unroll
                for (int nj = 0; nj < 4; ++nj) {
                    int col = 768 + j0 + warp_n * 32 + nj * 8 + t * 2;
                    *(__half2*)(g_At16 + (long)m * 1536 + col) =
                        __floats2half2_rn(acc[mi][nj][0], acc[mi][nj][1]);
                    *(__half2*)(g_At16 + (long)(m + 8) * 1536 + col) =
                        __floats2half2_rn(acc[mi][nj][2], acc[mi][nj][3]);
                }
            }
        } else {
            #pragma unroll
            for (int mi = 0; mi < 4; ++mi) {
                int m = m0 + warp_m * 64 + mi * 16 + g;
                #pragma unroll
                for (int nj = 0; nj < 4; ++nj) {
                    int col = j0 + warp_n * 32 + nj * 8 + t * 2;
                    float2 o0 = *(float2*)(Cacc + (long)m * JJ + col);
                    *(float2*)(Cacc + (long)m * JJ + col) =
                        make_float2(o0.x + acc[mi][nj][0], o0.y + acc[mi][nj][1]);
                    float2 o1 = *(float2*)(Cacc + (long)(m + 8) * JJ + col);
                    *(float2*)(Cacc + (long)(m + 8) * JJ + col) =
                        make_float2(o1.x + acc[mi][nj][2], o1.y + acc[mi][nj][3]);
                }
            }
        }
    }
    #undef ISSUE_STAGE
}

// ---------------- attn helpers ----------------
__device__ __forceinline__ void mm16(const float* __restrict__ sXt, const float* __restrict__ sWt,
                                     int tx, int ty, float acc[4][4]) {
    #pragma unroll 8
    for (int d = 0; d < 64; ++d) {
        float4 xv = *(const float4*)(sXt + d * PAD + ty * 4);
        float4 wv = *(const float4*)(sWt + d * PAD + tx * 4);
        float xs[4] = {xv.x, xv.y, xv.z, xv.w};
        float ws[4] = {wv.x, wv.y, wv.z, wv.w};
        #pragma unroll
        for (int i = 0; i < 4; ++i)
            #pragma unroll
            for (int j = 0; j < 4; ++j)
                acc[i][j] += xs[i] * ws[j];
    }
}
__device__ __forceinline__ void stage_xt(const float* __restrict__ src, long rowstride,
                                         float* __restrict__ dst, int tid) {
    #pragma unroll
    for (int it = 0; it < 4; ++it) {
        int idx = tid + it * 256;
        int r = idx >> 4;
        int c4 = (idx & 15) << 2;
        float4 f = *(const float4*)(src + (long)r * rowstride + c4);
        dst[(c4 + 0) * PAD + r] = f.x;
        dst[(c4 + 1) * PAD + r] = f.y;
        dst[(c4 + 2) * PAD + r] = f.z;
        dst[(c4 + 3) * PAD + r] = f.w;
    }
}

// ---------------- attention + output projection ----------------
__global__ __launch_bounds__(256) void attn_kernel(const float* __restrict__ Wo,
                                                   const float* __restrict__ bo,
                                                   float* __restrict__ out) {
    extern __shared__ float sm[];
    float* sXt = sm;                 // attn-out^T staging
    float* sWt = sm + 64 * PAD;
    float* sq = sm + 2 * 64 * PAD;
    float* sk = sm + 3 * 64 * PAD;
    float* sv = sm + 4 * 64 * PAD;

    const int n = blockIdx.x;
    const int b = blockIdx.y;
    const int tid = threadIdx.x;
    const int tx = tid & 15, ty = tid >> 4;

    // stage precomputed q/k/v
    #pragma unroll
    for (int i = 0; i < 4; ++i) {
        int idx = tid + (i << 8);
        int r = idx >> 4, c4 = (idx & 15) << 2;
        *(float4*)&sq[r * PAD + c4] = *(const float4*)(g_Qp + ((long)(b * 64 + r) * NN + n) * DD + c4);
        *(float4*)&sk[r * PAD + c4] = *(const float4*)(g_Kf + (long)n * JJ + b * 4096 + r * 64 + c4);
        *(float4*)&sv[r * PAD + c4] = *(const float4*)(g_Vf + (long)n * JJ + b * 4096 + r * 64 + c4);
    }
    stage_xt(Wo, DD, sWt, tid);
    __syncthreads();

    // attention: warp = head; lane handles query rows (lane, lane+32)
    {
        const int h = tid >> 5;
        const int lane = tid & 31;
        float qa[DK], qb[DK], aa[DK] = {}, ab[DK] = {};
        #pragma unroll
        for (int i = 0; i < DK; ++i) {
            qa[i] = sq[lane * PAD + h * DK + i];
            qb[i] = sq[(lane + 32) * PAD + h * DK + i];
        }
        float ma = -1e30f, mb = -1e30f, sa = 0.f, sb = 0.f;
        for (int s = 0; s < SS; ++s) {
            float da = 0.f, db = 0.f;
            #pragma unroll
            for (int i = 0; i < DK; ++i) {
                float kk = sk[s * PAD + h * DK + i];
                da += qa[i] * kk;
                db += qb[i] * kk;
            }
            float mna = fmaxf(ma, da), mnb = fmaxf(mb, db);
            float ca = __expf(ma - mna), pa = __expf(da - mna);
            float cb = __expf(mb - mnb), pb = __expf(db - mnb);
            sa = sa * ca + pa;
            sb = sb * cb + pb;
            ma = mna; mb = mnb;
            #pragma unroll
            for (int i = 0; i < DK; ++i) {
                float vv = sv[s * PAD + h * DK + i];
                aa[i] = aa[i] * ca + pa * vv;
                ab[i] = ab[i] * cb + pb * vv;
            }
        }
        float ra = 1.f / sa, rb = 1.f / sb;
        #pragma unroll
        for (int i = 0; i < DK; ++i) {
            sXt[(h * DK + i) * PAD + lane] = aa[i] * ra;
            sXt[(h * DK + i) * PAD + lane + 32] = ab[i] * rb;
        }
    }
    __syncthreads();

    // output projection
    {
        float acc[4][4] = {};
        mm16(sXt, sWt, tx, ty, acc);
        #pragma unroll
        for (int i = 0; i < 4; ++i) {
            int l = 4 * ty + i;
            float4 o = make_float4(acc[i][0] + bo[4 * tx + 0],
                                   acc[i][1] + bo[4 * tx + 1],
                                   acc[i][2] + bo[4 * tx + 2],
                                   acc[i][3] + bo[4 * tx + 3]);
            *(float4*)(out + ((long)(b * LL + l) * NN + n) * DD + 4 * tx) = o;
        }
    }
}

// ---------------- launch ----------------
extern "C" void kernel_launch(void* const* d_in, const int* in_sizes, int n_in,
                              void* d_out, int out_size) {
    const float* queries = (const float*)d_in[0];
    const float* keys    = (const float*)d_in[1];
    const float* values  = (const float*)d_in[2];
    const float* support = (const float*)d_in[3];
    const float* Wq = (const float*)d_in[4];
    const float* bq = (const float*)d_in[5];
    const float* Wk = (const float*)d_in[6];
    const float* bk = (const float*)d_in[7];
    const float* Wv = (const float*)d_in[8];
    const float* bv = (const float*)d_in[9];
    const float* Wo = (const float*)d_in[10];
    const float* bo = (const float*)d_in[11];
    const float* Wg1 = (const float*)d_in[12];
    const float* bg1 = (const float*)d_in[13];
    const float* Wg2 = (const float*)d_in[14];
    const float* bg2 = (const float*)d_in[15];
    float* out = (float*)d_out;

    cudaFuncSetAttribute(gemm_big_kernel, cudaFuncAttributeMaxDynamicSharedMemorySize, GEMM_SMEM);
    cudaFuncSetAttribute(proj_kernel, cudaFuncAttributeMaxDynamicSharedMemorySize, PROJ_SMEM);
    cudaFuncSetAttribute(attn_kernel, cudaFuncAttributeMaxDynamicSharedMemorySize,
                         5 * 64 * PAD * (int)sizeof(float));

    prep_split_kernel<<<2304, 256>>>(support);
    prep_w_kernel<<<2, 256>>>(Wk, bk, Wg1, bg1, Wv, bv, Wg2, bg2);

    // A2 = At @ support (fp16 stored into g_At16 cols 768+): 6 ntiles x 6 mtiles
    gemm_big_kernel<<<dim3(36, 1), 256, GEMM_SMEM>>>(0);
    // projections: P0 terms (+bias) into g_Kf/g_Vf/g_Qp, P1/P2 fp16 into P buffers
    proj_kernel<<<dim3(6, 256, 3), 256, PROJ_SMEM>>>(keys, values, queries, Wq, bq);
    // diffusion: C += [At|A2] @ [P1;P2]   (128 ntiles x 6 mtiles, paths K/V)
    gemm_big_kernel<<<dim3(768, 2), 256, GEMM_SMEM>>>(1);

    const int smem = 5 * 64 * PAD * (int)sizeof(float);
    attn_kernel<<<dim3(NN, BB), 256, smem>>>(Wo, bo, out);
}

// round 10
// speedup vs baseline: 2.5809x; 1.3140x over previous
#include <cuda_runtime.h>
#include <cuda_fp16.h>
#include <cstdint>

// Problem constants
#define BB 4
#define LL 64
#define SS 64
#define NN 768
#define DD 64
#define HH 8
#define DK 8
#define CING 192
#define JJ 16384   // B*S*D = 256*64

// ---------------- scratch (__device__ globals) ----------------
__device__ __half g_At16[NN * 1536];   // cols 0..767: At ; cols 768..1535: A2 (written by mode0)
__device__ __half g_Su16[NN * NN];     // support (B operand of mode0)
__device__ __half g_Pk[JJ * 1536];     // row j=bs*64+e: cols 0..767 = P1k^T, 768.. = P2k^T
__device__ __half g_Pv[JJ * 1536];
__device__ float g_Kf[NN * JJ];        // final projected K: [n][bs*64+e]
__device__ float g_Vf[NN * JJ];
__device__ __half g_Qp[256 * NN * DD]; // projected+scaled Q (fp16): [(b*64+l)][n][e]
__device__ float g_WkG1[DD * CING];
__device__ float g_WvG2[DD * CING];
__device__ float g_bk2[DD];
__device__ float g_bv2[DD];

// ================= PTX helpers (vanilla compute_103) =================
__device__ __forceinline__ uint32_t smem_u32_of(const void* p) {
    uint32_t a;
    asm("{ .reg .u64 t; cvta.to.shared.u64 t, %1; cvt.u32.u64 %0, t; }" : "=r"(a) : "l"(p));
    return a;
}
__device__ __forceinline__ void ldm_x4(uint32_t& r0, uint32_t& r1, uint32_t& r2, uint32_t& r3,
                                       uint32_t addr) {
    asm volatile("ldmatrix.sync.aligned.m8n8.x4.shared.b16 {%0,%1,%2,%3}, [%4];"
                 : "=r"(r0), "=r"(r1), "=r"(r2), "=r"(r3) : "r"(addr));
}
__device__ __forceinline__ void ldm_x4_t(uint32_t& r0, uint32_t& r1, uint32_t& r2, uint32_t& r3,
                                         uint32_t addr) {
    asm volatile("ldmatrix.sync.aligned.m8n8.x4.trans.shared.b16 {%0,%1,%2,%3}, [%4];"
                 : "=r"(r0), "=r"(r1), "=r"(r2), "=r"(r3) : "r"(addr));
}
__device__ __forceinline__ void ldm_x2(uint32_t& r0, uint32_t& r1, uint32_t addr) {
    asm volatile("ldmatrix.sync.aligned.m8n8.x2.shared.b16 {%0,%1}, [%2];"
                 : "=r"(r0), "=r"(r1) : "r"(addr));
}
__device__ __forceinline__ void mma_f16(float* c, const uint32_t* a, const uint32_t* b) {
    asm volatile("mma.sync.aligned.m16n8k16.row.col.f32.f16.f16.f32 "
                 "{%0,%1,%2,%3}, {%4,%5,%6,%7}, {%8,%9}, {%0,%1,%2,%3};"
                 : "+f"(c[0]), "+f"(c[1]), "+f"(c[2]), "+f"(c[3])
                 : "r"(a[0]), "r"(a[1]), "r"(a[2]), "r"(a[3]), "r"(b[0]), "r"(b[1]));
}
__device__ __forceinline__ void mma_f16_k8(float* c, uint32_t a0, uint32_t a1, uint32_t b0) {
    asm volatile("mma.sync.aligned.m16n8k8.row.col.f32.f16.f16.f32 "
                 "{%0,%1,%2,%3}, {%4,%5}, {%6}, {%0,%1,%2,%3};"
                 : "+f"(c[0]), "+f"(c[1]), "+f"(c[2]), "+f"(c[3])
                 : "r"(a0), "r"(a1), "r"(b0));
}
__device__ __forceinline__ void cp16(uint32_t saddr, const void* g) {
    asm volatile("cp.async.cg.shared.global [%0], [%1], 16;" :: "r"(saddr), "l"(g));
}
#define CP_COMMIT() asm volatile("cp.async.commit_group;")
#define CP_WAIT0()  asm volatile("cp.async.wait_group 0;")
#define CP_WAIT1()  asm volatile("cp.async.wait_group 1;")

__device__ __forceinline__ uint2 h4_of(float4 f) {
    __half2 a = __floats2half2_rn(f.x, f.y);
    __half2 b = __floats2half2_rn(f.z, f.w);
    return make_uint2(*(uint32_t*)&a, *(uint32_t*)&b);
}
__device__ __forceinline__ uint32_t h2pk(float x, float y) {
    __half2 h = __floats2half2_rn(x, y);
    return *(uint32_t*)&h;
}

// ---------------- prep: At + support -> fp16 ----------------
__global__ void prep_split_kernel(const float* __restrict__ a) {
    int idx = blockIdx.x * 256 + threadIdx.x;
    if (idx < NN * NN) {
        int n = idx / NN, v = idx - n * NN;
        g_At16[n * 1536 + v] = __float2half(a[v * NN + n]);   // At[n][v]
        g_Su16[idx] = __float2half(a[idx]);                   // support row-major
    }
}

// ---------------- prep: fold MLP weight into K/V projections ----------------
__global__ void prep_w_kernel(const float* __restrict__ Wk, const float* __restrict__ bk,
                              const float* __restrict__ Wg1, const float* __restrict__ bg1,
                              const float* __restrict__ Wv, const float* __restrict__ bv,
                              const float* __restrict__ Wg2, const float* __restrict__ bg2) {
    const float* W1 = blockIdx.x ? Wv : Wk;
    const float* Wg = blockIdx.x ? Wg2 : Wg1;
    const float* bg = blockIdx.x ? bg2 : bg1;
    const float* bb = blockIdx.x ? bv : bk;
    float* WG = blockIdx.x ? g_WvG2 : g_WkG1;
    float* b2 = blockIdx.x ? g_bv2 : g_bk2;

    __shared__ float sW[DD * DD];
    for (int i = threadIdx.x; i < DD * DD; i += 256) sW[i] = W1[i];
    __syncthreads();

    for (int idx = threadIdx.x; idx < DD * CING; idx += 256) {
        int e = idx / CING;
        int c = idx - e * CING;
        float s = 0.f;
        #pragma unroll 8
        for (int o = 0; o < DD; ++o) s += sW[e * DD + o] * Wg[o * CING + c];
        WG[idx] = s;
    }
    if (threadIdx.x < DD) {
        float s = 0.f;
        for (int o = 0; o < DD; ++o) s += sW[threadIdx.x * DD + o] * bg[o];
        b2[threadIdx.x] = s + bb[threadIdx.x];
    }
}

// =========================================================================
// proj kernel: per (ntile, bs, path) with X tile 128 rows x 64 ch (fp16 MMA).
//  pass a: C1[n][e] = X @ W0^T (+bias [,*scale]) -> output buffer (P0 term)
//  pass b (K/V only): C2[e'][n] = Wstack(W1;W2) @ X^T -> fp16 into P buffers
// =========================================================================
#define PJ_X 0
#define PJ_W 18432
#define PROJ_SMEM 46080

__global__ __launch_bounds__(256) void proj_kernel(const float* __restrict__ keys,
                                                   const float* __restrict__ values,
                                                   const float* __restrict__ queries,
                                                   const float* __restrict__ Wq,
                                                   const float* __restrict__ bq) {
    extern __shared__ char smem[];
    const uint32_t smem_b = smem_u32_of(smem);
    const int tid = threadIdx.x, wid = tid >> 5, lane = tid & 31;
    const int warp_m = wid & 1, warp_n = wid >> 1;
    const int ntile = blockIdx.x;     // 0..5
    const int bs = blockIdx.y;        // 0..255
    const int path = blockIdx.z;      // 0 K, 1 V, 2 Q
    const int n0 = ntile * 128;

    const float* X = (path == 0) ? keys : (path == 1) ? values : queries;
    X += (long)bs * NN * DD;
    const float* WG = (path == 0) ? g_WkG1 : g_WvG2;

    // stage X (128 x 64) -> fp16, 144B rows
    #pragma unroll
    for (int i = 0; i < 8; ++i) {
        int idx = tid + (i << 8);
        int r = idx >> 4, c4 = (idx & 15) << 2;
        float4 f = *(const float4*)(X + (long)(n0 + r) * DD + c4);
        *(uint2*)(smem + PJ_X + r * 144 + c4 * 2) = h4_of(f);
    }
    // stage W (192 rows x 64) -> fp16
    #pragma unroll
    for (int i = 0; i < 12; ++i) {
        int idx = tid + (i << 8);
        int r = idx >> 4, c4 = (idx & 15) << 2;
        float4 f;
        if (path == 2) {
            f = (r < 64) ? *(const float4*)(Wq + r * DD + c4) : make_float4(0.f, 0.f, 0.f, 0.f);
        } else {
            int er = (r < 64) ? r : (r < 128 ? r - 64 : r - 128);
            int co = (r < 64) ? 0 : (r < 128 ? 64 : 128);
            f = *(const float4*)(WG + er * CING + co + c4);
        }
        *(uint2*)(smem + PJ_W + r * 144 + c4 * 2) = h4_of(f);
    }
    __syncthreads();

    const int a_r = lane & 15, a_c = (lane >> 4) << 3;
    const int b_m = lane >> 3;
    const int b_n = (lane & 7) + ((b_m >> 1) << 3);
    const int b_k = (b_m & 1) << 3;
    const int g = lane >> 2, t = lane & 3;

    // ---- pass a: C1[n 128][e 64] = X @ W0^T ----
    {
        float acc[4][2][4] = {};
        const uint32_t abase = smem_b + (warp_m * 64 + a_r) * 144 + a_c * 2;
        const uint32_t bbase = smem_b + (warp_n * 16 + b_n) * 144 + b_k * 2;
        #pragma unroll
        for (int kc = 0; kc < 4; ++kc) {
            uint32_t kO = kc * 32;
            uint32_t ah[4][4], bh[2][2];
            #pragma unroll
            for (int mi = 0; mi < 4; ++mi) {
                uint32_t ad = abase + mi * 2304 + kO;
                ldm_x4(ah[mi][0], ah[mi][1], ah[mi][2], ah[mi][3], ad + PJ_X);
            }
            ldm_x4(bh[0][0], bh[0][1], bh[1][0], bh[1][1], bbase + PJ_W + kO);
            #pragma unroll
            for (int mi = 0; mi < 4; ++mi)
                #pragma unroll
                for (int nj = 0; nj < 2; ++nj)
                    mma_f16(acc[mi][nj], ah[mi], bh[nj]);
        }
        #pragma unroll
        for (int mi = 0; mi < 4; ++mi)
            #pragma unroll
            for (int nj = 0; nj < 2; ++nj) {
                int nr = n0 + warp_m * 64 + mi * 16 + g;
                int e = warp_n * 16 + nj * 8 + t * 2;
                if (path == 2) {
                    const float sc = 0.35355339059327373f;
                    *(__half2*)(g_Qp + ((long)bs * NN + nr) * DD + e) =
                        __floats2half2_rn(acc[mi][nj][0] * sc + bq[e] * sc,
                                          acc[mi][nj][1] * sc + bq[e + 1] * sc);
                    *(__half2*)(g_Qp + ((long)bs * NN + nr + 8) * DD + e) =
                        __floats2half2_rn(acc[mi][nj][2] * sc + bq[e] * sc,
                                          acc[mi][nj][3] * sc + bq[e + 1] * sc);
                } else {
                    float* Cout = path ? g_Vf : g_Kf;
                    const float* bias = path ? g_bv2 : g_bk2;
                    *(float2*)(Cout + (long)nr * JJ + bs * 64 + e) =
                        make_float2(acc[mi][nj][0] + bias[e], acc[mi][nj][1] + bias[e + 1]);
                    *(float2*)(Cout + (long)(nr + 8) * JJ + bs * 64 + e) =
                        make_float2(acc[mi][nj][2] + bias[e], acc[mi][nj][3] + bias[e + 1]);
                }
            }
    }

    // ---- pass b: C2[e' 128][n 128] = Wstack @ X^T -> fp16 store ----
    if (path < 2) {
        float acc[4][4][4] = {};
        const uint32_t abase = smem_b + (64 + warp_m * 64 + a_r) * 144 + a_c * 2;
        const uint32_t bbase = smem_b + (warp_n * 32 + b_n) * 144 + b_k * 2;
        #pragma unroll
        for (int kc = 0; kc < 4; ++kc) {
            uint32_t kO = kc * 32;
            uint32_t ah[4][4], bh[4][2];
            #pragma unroll
            for (int mi = 0; mi < 4; ++mi) {
                uint32_t ad = abase + mi * 2304 + kO;
                ldm_x4(ah[mi][0], ah[mi][1], ah[mi][2], ah[mi][3], ad + PJ_W);
            }
            #pragma unroll
            for (int p = 0; p < 2; ++p) {
                uint32_t bd = bbase + p * 2304 + kO;
                ldm_x4(bh[2 * p][0], bh[2 * p][1], bh[2 * p + 1][0], bh[2 * p + 1][1], bd + PJ_X);
            }
            #pragma unroll
            for (int mi = 0; mi < 4; ++mi)
                #pragma unroll
                for (int nj = 0; nj < 4; ++nj)
                    mma_f16(acc[mi][nj], ah[mi], bh[nj]);
        }
        __half* P = path ? g_Pv : g_Pk;
        #pragma unroll
        for (int mi = 0; mi < 4; ++mi)
            #pragma unroll
            for (int nj = 0; nj < 4; ++nj) {
                int ep = warp_m * 64 + mi * 16 + g;
                int nl = n0 + warp_n * 32 + nj * 8 + t * 2;
                long row0 = (long)bs * 64 + (ep & 63);
                long col = (long)(ep >> 6) * 768 + nl;
                *(__half2*)(P + row0 * 1536 + col) = __floats2half2_rn(acc[mi][nj][0], acc[mi][nj][1]);
                long row1 = (long)bs * 64 + ((ep + 8) & 63);
                *(__half2*)(P + row1 * 1536 + col) = __floats2half2_rn(acc[mi][nj][2], acc[mi][nj][3]);
            }
    }
}

// =========================================================================
// big GEMM (cp.async, fp16), tile 128(M) x 128(N), Kc=64,
// 3 smem stages with 2 copies in flight, 2 CTAs/SM.
// mode 0: A2 = At @ support : grid (36,1), k=768, fp16 store -> g_At16 cols 768+
// mode 1: C += [At|A2] @ [P1;P2] : grid (768,2), k=1536, fp32 RMW epilogue
// =========================================================================
#define O_A 0
#define O_B 18432
#define STAGEB 36864
#define GEMM_SMEM (3 * STAGEB)   // 108 KB -> 2 CTAs/SM

__global__ __launch_bounds__(256, 2) void gemm_big_kernel(int mode) {
    extern __shared__ char smem[];
    const uint32_t smem_b = smem_u32_of(smem);
    const int tid = threadIdx.x, wid = tid >> 5, lane = tid & 31;
    const int warp_m = wid & 1, warp_n = wid >> 1;
    const int mtile = blockIdx.x % 6, ntile = blockIdx.x / 6;
    const int m0 = mtile * 128, j0 = ntile * 128;

    const __half* Ap = g_At16;
    const __half* Bp;
    long sB;
    int ktiles;
    float* Cacc = nullptr;
    if (mode == 0) {
        Bp = g_Su16; sB = NN; ktiles = 12;
    } else {
        int p = blockIdx.y;
        Bp = p ? g_Pv : g_Pk;
        sB = 1536; ktiles = 24;
        Cacc = p ? g_Vf : g_Kf;
    }
    const long sA = 1536;

    #define ISSUE_STAGE(kt)                                                      \
        {                                                                        \
            uint32_t st = smem_b + ((kt) % 3) * STAGEB;                          \
            long ko = (long)(kt) * 64;                                           \
            _Pragma("unroll")                                                    \
            for (int i = 0; i < 4; ++i) {                                        \
                int ch = tid + (i << 8);                                         \
                int r = ch >> 3, c = ch & 7;                                     \
                uint32_t so = st + r * 144 + c * 16;                             \
                cp16(so + O_A, Ap + (long)(m0 + r) * sA + ko + c * 8);           \
                cp16(so + O_B, Bp + (long)(j0 + r) * sB + ko + c * 8);           \
            }                                                                    \
            CP_COMMIT();                                                         \
        }

    float acc[4][4][4] = {};   // [m-atom][n-atom][4]

    const int a_r = lane & 15, a_c = (lane >> 4) << 3;
    const int b_m = lane >> 3;
    const int b_n = (lane & 7) + ((b_m >> 1) << 3);
    const int b_k = (b_m & 1) << 3;
    const uint32_t a_base = (uint32_t)((warp_m * 64 + a_r) * 144 + a_c * 2);
    const uint32_t b_base = (uint32_t)((warp_n * 32 + b_n) * 144 + b_k * 2);

    ISSUE_STAGE(0);
    if (ktiles > 1) ISSUE_STAGE(1);

    for (int kt = 0; kt < ktiles; ++kt) {
        if (kt + 1 < ktiles) CP_WAIT1(); else CP_WAIT0();
        __syncthreads();
        if (kt + 2 < ktiles) ISSUE_STAGE(kt + 2);

        const uint32_t sbase = smem_b + (kt % 3) * STAGEB;
        #pragma unroll
        for (int kc = 0; kc < 4; ++kc) {
            const uint32_t kO = kc * 32;
            uint32_t ah[4][4], bh[4][2];
            #pragma unroll
            for (int mi = 0; mi < 4; ++mi) {
                uint32_t ad = sbase + a_base + mi * 2304 + kO;
                ldm_x4(ah[mi][0], ah[mi][1], ah[mi][2], ah[mi][3], ad + O_A);
            }
            #pragma unroll
            for (int p = 0; p < 2; ++p) {
                uint32_t bd = sbase + b_base + p * 2304 + kO;
                ldm_x4(bh[2 * p][0], bh[2 * p][1], bh[2 * p + 1][0], bh[2 * p + 1][1], bd + O_B);
            }
            #pragma unroll
            for (int mi = 0; mi < 4; ++mi)
                #pragma unroll
                for (int nj = 0; nj < 4; ++nj)
                    mma_f16(acc[mi][nj], ah[mi], bh[nj]);
        }
    }

    __syncthreads();
    {
        const int g = lane >> 2, t = lane & 3;
        if (mode == 0) {
            #pragma unroll
            for (int mi = 0; mi < 4; ++mi) {
                int m = m0 + warp_m * 64 + mi * 16 + g;
                #pragma unroll
                for (int nj = 0; nj < 4; ++nj) {
                    int col = 768 + j0 + warp_n * 32 + nj * 8 + t * 2;
                    *(__half2*)(g_At16 + (long)m * 1536 + col) =
                        __floats2half2_rn(acc[mi][nj][0], acc[mi][nj][1]);
                    *(__half2*)(g_At16 + (long)(m + 8) * 1536 + col) =
                        __floats2half2_rn(acc[mi][nj][2], acc[mi][nj][3]);
                }
            }
        } else {
            #pragma unroll
            for (int mi = 0; mi < 4; ++mi) {
                int m = m0 + warp_m * 64 + mi * 16 + g;
                #pragma unroll
                for (int nj = 0; nj < 4; ++nj) {
                    int col = j0 + warp_n * 32 + nj * 8 + t * 2;
                    float2 o0 = *(float2*)(Cacc + (long)m * JJ + col);
                    *(float2*)(Cacc + (long)m * JJ + col) =
                        make_float2(o0.x + acc[mi][nj][0], o0.y + acc[mi][nj][1]);
                    float2 o1 = *(float2*)(Cacc + (long)(m + 8) * JJ + col);
                    *(float2*)(Cacc + (long)(m + 8) * JJ + col) =
                        make_float2(o1.x + acc[mi][nj][2], o1.y + acc[mi][nj][3]);
                }
            }
        }
    }
    #undef ISSUE_STAGE
}

// =========================================================================
// attention (flash-style MMA) + output projection, per (b, n) block.
// warp = head for attention; smem fp16 tiles with 72-half (144B) rows.
// =========================================================================
#define SQ_OFF 0
#define SK_OFF (64 * 72)
#define SV_OFF (2 * 64 * 72)
#define SO_OFF (3 * 64 * 72)
#define SW_OFF (4 * 64 * 72)
#define ATT_SMEM (5 * 64 * 72 * 2)   // 46080 bytes

__global__ __launch_bounds__(256) void attn_kernel(const float* __restrict__ Wo,
                                                   const float* __restrict__ bo,
                                                   float* __restrict__ out) {
    extern __shared__ __half sh[];
    const uint32_t sb = smem_u32_of(sh);
    const int n = blockIdx.x, b = blockIdx.y;
    const int tid = threadIdx.x, wid = tid >> 5, lane = tid & 31;
    const int t = lane & 3;

    // stage Q (fp16 copy), K/V/Wo (fp32 -> fp16)
    #pragma unroll
    for (int i = 0; i < 4; ++i) {
        int idx = tid + (i << 8);
        int r = idx >> 4, c4 = (idx & 15) << 2;
        *(uint2*)(sh + SQ_OFF + r * 72 + c4) =
            *(const uint2*)(g_Qp + ((long)(b * 64 + r) * NN + n) * DD + c4);
        float4 fk = *(const float4*)(g_Kf + (long)n * JJ + b * 4096 + r * 64 + c4);
        *(uint2*)(sh + SK_OFF + r * 72 + c4) = h4_of(fk);
        float4 fv = *(const float4*)(g_Vf + (long)n * JJ + b * 4096 + r * 64 + c4);
        *(uint2*)(sh + SV_OFF + r * 72 + c4) = h4_of(fv);
        float4 fw = *(const float4*)(Wo + r * 64 + c4);
        *(uint2*)(sh + SW_OFF + r * 72 + c4) = h4_of(fw);
    }
    __syncthreads();

    const int h = wid;   // head
    #pragma unroll
    for (int hp = 0; hp < 2; ++hp) {
        const int l0 = hp * 32;
        uint32_t qf[4], kf[8], vf[8];
        // Q fragments: rows l0..l0+31 (2 m-atoms), cols h*8..h*8+7
        ldm_x4(qf[0], qf[1], qf[2], qf[3], sb + (SQ_OFF + (l0 + lane) * 72 + h * 8) * 2);
        // K fragments: 8 n-atoms (s 0..63)
        ldm_x4(kf[0], kf[1], kf[2], kf[3], sb + (SK_OFF + lane * 72 + h * 8) * 2);
        ldm_x4(kf[4], kf[5], kf[6], kf[7], sb + (SK_OFF + (32 + lane) * 72 + h * 8) * 2);

        // S = Q K^T  (K = DK = 8)
        float S[2][8][4];
        #pragma unroll
        for (int mi = 0; mi < 2; ++mi)
            #pragma unroll
            for (int nj = 0; nj < 8; ++nj) {
                S[mi][nj][0] = S[mi][nj][1] = S[mi][nj][2] = S[mi][nj][3] = 0.f;
                mma_f16_k8(S[mi][nj], qf[2 * mi], qf[2 * mi + 1], kf[nj]);
            }

        // V fragments for PV (4 k16-atoms)
        ldm_x4_t(vf[0], vf[1], vf[2], vf[3], sb + (SV_OFF + lane * 72 + h * 8) * 2);
        ldm_x4_t(vf[4], vf[5], vf[6], vf[7], sb + (SV_OFF + (32 + lane) * 72 + h * 8) * 2);

        #pragma unroll
        for (int mi = 0; mi < 2; ++mi) {
            // row max (rows r = lane/4 and r+8)
            float mx0 = -1e30f, mx1 = -1e30f;
            #pragma unroll
            for (int nj = 0; nj < 8; ++nj) {
                mx0 = fmaxf(mx0, fmaxf(S[mi][nj][0], S[mi][nj][1]));
                mx1 = fmaxf(mx1, fmaxf(S[mi][nj][2], S[mi][nj][3]));
            }
            mx0 = fmaxf(mx0, __shfl_xor_sync(0xffffffffu, mx0, 1));
            mx0 = fmaxf(mx0, __shfl_xor_sync(0xffffffffu, mx0, 2));
            mx1 = fmaxf(mx1, __shfl_xor_sync(0xffffffffu, mx1, 1));
            mx1 = fmaxf(mx1, __shfl_xor_sync(0xffffffffu, mx1, 2));
            // exp + row sums
            float sum0 = 0.f, sum1 = 0.f;
            #pragma unroll
            for (int nj = 0; nj < 8; ++nj) {
                S[mi][nj][0] = __expf(S[mi][nj][0] - mx0);
                S[mi][nj][1] = __expf(S[mi][nj][1] - mx0);
                S[mi][nj][2] = __expf(S[mi][nj][2] - mx1);
                S[mi][nj][3] = __expf(S[mi][nj][3] - mx1);
                sum0 += S[mi][nj][0] + S[mi][nj][1];
                sum1 += S[mi][nj][2] + S[mi][nj][3];
            }
            sum0 += __shfl_xor_sync(0xffffffffu, sum0, 1);
            sum0 += __shfl_xor_sync(0xffffffffu, sum0, 2);
            sum1 += __shfl_xor_sync(0xffffffffu, sum1, 1);
            sum1 += __shfl_xor_sync(0xffffffffu, sum1, 2);

            // O = P V  (pack P accum -> A fragments)
            float O[4] = {};
            #pragma unroll
            for (int ka = 0; ka < 4; ++ka) {
                uint32_t pa[4];
                pa[0] = h2pk(S[mi][2 * ka][0], S[mi][2 * ka][1]);
                pa[1] = h2pk(S[mi][2 * ka][2], S[mi][2 * ka][3]);
                pa[2] = h2pk(S[mi][2 * ka + 1][0], S[mi][2 * ka + 1][1]);
                pa[3] = h2pk(S[mi][2 * ka + 1][2], S[mi][2 * ka + 1][3]);
                mma_f16(O, pa, &vf[2 * ka]);
            }
            float i0 = 1.f / sum0, i1 = 1.f / sum1;
            int row = l0 + mi * 16 + (lane >> 2);
            *(__half2*)(sh + SO_OFF + row * 72 + h * 8 + 2 * t) =
                __floats2half2_rn(O[0] * i0, O[1] * i0);
            *(__half2*)(sh + SO_OFF + (row + 8) * 72 + h * 8 + 2 * t) =
                __floats2half2_rn(O[2] * i1, O[3] * i1);
        }
    }
    __syncthreads();

    // output projection: out[l][e] = O_all[l][:] @ Wo[e][:] + bo
    {
        const int mi = wid & 3, njg = wid >> 2;
        uint32_t af[4][4], bf[4][4][2];
        #pragma unroll
        for (int ka = 0; ka < 4; ++ka)
            ldm_x4(af[ka][0], af[ka][1], af[ka][2], af[ka][3],
                   sb + (SO_OFF + (mi * 16 + (lane & 15)) * 72 + ka * 16 + ((lane >> 4) << 3)) * 2);
        #pragma unroll
        for (int nj = 0; nj < 4; ++nj)
            #pragma unroll
            for (int ka = 0; ka < 4; ++ka)
                ldm_x2(bf[ka][nj][0], bf[ka][nj][1],
                       sb + (SW_OFF + (njg * 32 + nj * 8 + (lane & 7)) * 72 + ka * 16 +
                             (((lane >> 3) & 1) << 3)) * 2);
        float C[4][4] = {};
        #pragma unroll
        for (int ka = 0; ka < 4; ++ka)
            #pragma unroll
            for (int nj = 0; nj < 4; ++nj)
                mma_f16(C[nj], af[ka], bf[ka][nj]);

        const int l = mi * 16 + (lane >> 2);
        #pragma unroll
        for (int nj = 0; nj < 4; ++nj) {
            int e = njg * 32 + nj * 8 + 2 * t;
            float b0v = bo[e], b1v = bo[e + 1];
            *(float2*)(out + ((long)(b * 64 + l) * NN + n) * DD + e) =
                make_float2(C[nj][0] + b0v, C[nj][1] + b1v);
            *(float2*)(out + ((long)(b * 64 + l + 8) * NN + n) * DD + e) =
                make_float2(C[nj][2] + b0v, C[nj][3] + b1v);
        }
    }
}

// ---------------- launch ----------------
extern "C" void kernel_launch(void* const* d_in, const int* in_sizes, int n_in,
                              void* d_out, int out_size) {
    const float* queries = (const float*)d_in[0];
    const float* keys    = (const float*)d_in[1];
    const float* values  = (const float*)d_in[2];
    const float* support = (const float*)d_in[3];
    const float* Wq = (const float*)d_in[4];
    const float* bq = (const float*)d_in[5];
    const float* Wk = (const float*)d_in[6];
    const float* bk = (const float*)d_in[7];
    const float* Wv = (const float*)d_in[8];
    const float* bv = (const float*)d_in[9];
    const float* Wo = (const float*)d_in[10];
    const float* bo = (const float*)d_in[11];
    const float* Wg1 = (const float*)d_in[12];
    const float* bg1 = (const float*)d_in[13];
    const float* Wg2 = (const float*)d_in[14];
    const float* bg2 = (const float*)d_in[15];
    float* out = (float*)d_out;

    cudaFuncSetAttribute(gemm_big_kernel, cudaFuncAttributeMaxDynamicSharedMemorySize, GEMM_SMEM);
    cudaFuncSetAttribute(proj_kernel, cudaFuncAttributeMaxDynamicSharedMemorySize, PROJ_SMEM);
    cudaFuncSetAttribute(attn_kernel, cudaFuncAttributeMaxDynamicSharedMemorySize, ATT_SMEM);

    prep_split_kernel<<<2304, 256>>>(support);
    prep_w_kernel<<<2, 256>>>(Wk, bk, Wg1, bg1, Wv, bv, Wg2, bg2);

    // A2 = At @ support (fp16 stored into g_At16 cols 768+): 6 ntiles x 6 mtiles
    gemm_big_kernel<<<dim3(36, 1), 256, GEMM_SMEM>>>(0);
    // projections: P0 terms (+bias) into g_Kf/g_Vf/g_Qp, P1/P2 fp16 into P buffers
    proj_kernel<<<dim3(6, 256, 3), 256, PROJ_SMEM>>>(keys, values, queries, Wq, bq);
    // diffusion: C += [At|A2] @ [P1;P2]   (128 ntiles x 6 mtiles, paths K/V)
    gemm_big_kernel<<<dim3(768, 2), 256, GEMM_SMEM>>>(1);

    attn_kernel<<<dim3(NN, BB), 256, ATT_SMEM>>>(Wo, bo, out);
}